// round 12
// baseline (speedup 1.0000x reference)
#include <cuda_runtime.h>
#include <cuda_bf16.h>
#include <math.h>

// ---------------------------------------------------------------------------
// RDAB block: x[16,64,128,128] fp32
// Round 12: mma.sync bf16 conv, 4 rows/block (512 thr), cp.async double
// buffering; gate2 (1x1 conv + sigmoid) fused into conv1's epilogue via
// butterfly shuffle over co-lanes.
// ---------------------------------------------------------------------------

#define B_   16
#define C_   64
#define H_   128
#define W_   128
#define HW_  (H_*W_)
#define CHW_ (C_*HW_)

typedef unsigned long long u64;
typedef unsigned int u32;
typedef unsigned short u16;

__device__ u32   g_buf1[(size_t)B_*CHW_];   // packed (bf16hi<<16)|bf16lo
__device__ float g_buf2[(size_t)B_*CHW_];
__device__ float g_gate[(size_t)B_*HW_];
__device__ float g_kern1[B_*C_*9];
__device__ float g_kern2[B_*C_*9];
// fragment-ordered weights: [conv2][chunk4][step9][mt4][half2][lane32][reg4] u32
__device__ u32   g_wA[2*4*9*4*2*32*4];

__device__ __forceinline__ float leaky01(float v) { return v > 0.f ? v : 0.1f*v; }

__device__ __forceinline__ u32 pack_hilo(float v) {
    __nv_bfloat16 h = __float2bfloat16(v);
    float vh = __bfloat162float(h);
    __nv_bfloat16 l = __float2bfloat16(v - vh);
    u16 hb = *reinterpret_cast<u16*>(&h);
    u16 lb = *reinterpret_cast<u16*>(&l);
    return ((u32)hb << 16) | (u32)lb;
}
__device__ __forceinline__ void mma16816(float* c, const u32* a, u32 b0, u32 b1) {
    asm volatile(
        "mma.sync.aligned.m16n8k16.row.col.f32.bf16.bf16.f32 "
        "{%0,%1,%2,%3}, {%4,%5,%6,%7}, {%8,%9}, {%0,%1,%2,%3};"
        : "+f"(c[0]), "+f"(c[1]), "+f"(c[2]), "+f"(c[3])
        : "r"(a[0]), "r"(a[1]), "r"(a[2]), "r"(a[3]), "r"(b0), "r"(b1));
}
__device__ __forceinline__ u32 smem_u32(const void* p) {
    u32 a;
    asm("{ .reg .u64 t; cvta.to.shared.u64 t, %1; cvt.u32.u64 %0, t; }"
        : "=r"(a) : "l"(p));
    return a;
}
__device__ __forceinline__ void cp_async16(u32 dst, const void* src) {
    asm volatile("cp.async.ca.shared.global [%0], [%1], 16;\n" :: "r"(dst), "l"(src));
}
__device__ __forceinline__ void cp_commit() { asm volatile("cp.async.commit_group;\n"); }
__device__ __forceinline__ void cp_wait_all() { asm volatile("cp.async.wait_group 0;\n"); }

// ---------------------------------------------------------------------------
// 1) dynamic-kernel MLP
// ---------------------------------------------------------------------------
__global__ void mlp_kernel(const float* __restrict__ d,
                           const float* __restrict__ k1a, const float* __restrict__ k2a,
                           const float* __restrict__ k1b, const float* __restrict__ k2b,
                           float* __restrict__ kern1, float* __restrict__ kern2)
{
    int b = blockIdx.x, stage = blockIdx.y;
    const float* k1 = stage ? k1b : k1a;
    const float* k2 = stage ? k2b : k2a;
    float* ko = stage ? kern2 : kern1;
    __shared__ float dd[64], hid[64];
    int t = threadIdx.x;
    dd[t] = d[b*64 + t];
    __syncthreads();
    float s = 0.f;
#pragma unroll 8
    for (int i = 0; i < 64; i++) s += dd[i] * k1[i*64 + t];
    hid[t] = leaky01(s);
    __syncthreads();
#pragma unroll
    for (int r = 0; r < 9; r++) {
        int o = r*64 + t;
        float s2 = 0.f;
#pragma unroll 8
        for (int i = 0; i < 64; i++) s2 += hid[i] * k2[i*576 + o];
        ko[b*576 + o] = s2;
    }
}

// ---------------------------------------------------------------------------
// 2) gating map from fp32 input (only needed for stage 1, from x)
// ---------------------------------------------------------------------------
__global__ void gate_kernel(const float* __restrict__ in,
                            const float* __restrict__ cw,
                            const float* __restrict__ cb,
                            float* __restrict__ M)
{
    __shared__ float scw[C_];
    if (threadIdx.x < C_) scw[threadIdx.x] = cw[threadIdx.x];
    __syncthreads();
    int idx4 = blockIdx.x * blockDim.x + threadIdx.x;
    int b = idx4 / (HW_/4);
    int hw4 = idx4 - b * (HW_/4);
    const float* p = in + (size_t)b * CHW_ + hw4 * 4;
    float bias = cb[0];
    float4 s = make_float4(bias, bias, bias, bias);
#pragma unroll 8
    for (int c = 0; c < C_; c++) {
        float4 v = *(const float4*)(p + (size_t)c * HW_);
        float w = scw[c];
        s.x += w*v.x; s.y += w*v.y; s.z += w*v.z; s.w += w*v.w;
    }
    float4 r;
    r.x = 1.f/(1.f+expf(-s.x)); r.y = 1.f/(1.f+expf(-s.y));
    r.z = 1.f/(1.f+expf(-s.z)); r.w = 1.f/(1.f+expf(-s.w));
    *(float4*)&M[(size_t)b*HW_ + hw4*4] = r;
}

// ---------------------------------------------------------------------------
// 3) fused RDA, float4 — writes PACKED (bf16hi<<16|bf16lo)
// ---------------------------------------------------------------------------
__global__ void rda_kernel(const float* __restrict__ in,
                           const float* __restrict__ kern,
                           const float* __restrict__ M,
                           u32* __restrict__ outp)
{
    int idx4 = blockIdx.x * blockDim.x + threadIdx.x;
    int c = blockIdx.y, b = blockIdx.z;
    int h  = idx4 >> 5;
    int wq = (idx4 & 31) * 4;

    const float* k = kern + (b*C_ + c) * 9;
    float kk[9];
#pragma unroll
    for (int i = 0; i < 9; i++) kk[i] = k[i];

    const float* p = in + ((size_t)b*C_ + c) * HW_;
    float4 dw = make_float4(0.f, 0.f, 0.f, 0.f);
    float4 mid_c = *(const float4*)(p + h * W_ + wq);

#pragma unroll
    for (int r = 0; r < 3; r++) {
        int gy = h - 1 + r;
        if (gy < 0 || gy >= H_) continue;
        const float* rowp = p + gy * W_;
        float4 mid = (r == 1) ? mid_c : *(const float4*)(rowp + wq);
        float left  = (wq > 0)   ? rowp[wq - 1] : 0.f;
        float right = (wq < 124) ? rowp[wq + 4] : 0.f;
        float t0 = kk[r*3+0], t1 = kk[r*3+1], t2 = kk[r*3+2];
        dw.x += t0*left  + t1*mid.x + t2*mid.y;
        dw.y += t0*mid.x + t1*mid.y + t2*mid.z;
        dw.z += t0*mid.y + t1*mid.z + t2*mid.w;
        dw.w += t0*mid.z + t1*mid.w + t2*right;
    }

    float4 m = *(const float4*)&M[(size_t)b*HW_ + h*W_ + wq];
    uint4 o;
    o.x = pack_hilo(leaky01(leaky01(dw.x)*m.x + mid_c.x));
    o.y = pack_hilo(leaky01(leaky01(dw.y)*m.y + mid_c.y));
    o.z = pack_hilo(leaky01(leaky01(dw.z)*m.z + mid_c.z));
    o.w = pack_hilo(leaky01(leaky01(dw.w)*m.w + mid_c.w));
    *(uint4*)&outp[((size_t)b*C_ + c)*HW_ + h*W_ + wq] = o;
}

// ---------------------------------------------------------------------------
// 3b) weight prep: fp32 OIHW -> bf16 hi/lo in m16n8k16 A-fragment order.
// ---------------------------------------------------------------------------
__global__ void wprep_kernel(const float* __restrict__ w1,
                             const float* __restrict__ w2)
{
    int idx = blockIdx.x * blockDim.x + threadIdx.x;
    if (idx >= 2*4*9*4*2*32*4) return;
    int t = idx;
    int r    = t & 3;  t >>= 2;
    int lane = t & 31; t >>= 5;
    int q    = t & 1;  t >>= 1;
    int mt   = t & 3;  t >>= 2;
    int s9   = t % 9;  t /= 9;
    int chunk= t & 3;  t >>= 2;
    int s2   = t;

    int g = lane >> 2, tig = lane & 3;
    int co = mt*16 + g + (r & 1)*8;
    int k0 = s9*16 + 2*tig + (r >> 1)*8;
    int k1 = k0 + 1;

    const float* w = s2 ? w2 : w1;
    int ci0 = k0/9, tap0 = k0 - ci0*9;
    int ci1 = k1/9, tap1 = k1 - ci1*9;
    float w0 = w[(co*C_ + chunk*16 + ci0)*9 + tap0];
    float w1v= w[(co*C_ + chunk*16 + ci1)*9 + tap1];

    u16 p0, p1;
    if (q == 0) {
        __nv_bfloat16 h0 = __float2bfloat16(w0), h1 = __float2bfloat16(w1v);
        p0 = *reinterpret_cast<u16*>(&h0); p1 = *reinterpret_cast<u16*>(&h1);
    } else {
        __nv_bfloat16 h0 = __float2bfloat16(w0);
        __nv_bfloat16 l0 = __float2bfloat16(w0 - __bfloat162float(h0));
        __nv_bfloat16 h1 = __float2bfloat16(w1v);
        __nv_bfloat16 l1 = __float2bfloat16(w1v - __bfloat162float(h1));
        p0 = *reinterpret_cast<u16*>(&l0); p1 = *reinterpret_cast<u16*>(&l1);
    }
    g_wA[idx] = ((u32)p1 << 16) | (u32)p0;
}

// ---------------------------------------------------------------------------
// 4) mma.sync conv v3: block = 4 rows, 512 threads = 16 warps.
//    wg = wid>>2 handles row h0+wg; warp (wid&3) covers 32 px, all 64 co.
//    Double-buffered cp.async weights + input (16 ci x 6 rows x RW2 u32).
//    Optional fused gate: M = sigmoid(sum_co out*gcw[co] + gcb) via shuffles.
// ---------------------------------------------------------------------------
#define RW2  136
#define WCH  9216                        // u32 per weight chunk
#define ICH  (16*6*RW2)                  // 13056 u32 per input chunk
#define SMEM_DYN ((2*WCH + 2*ICH) * 4)   // 178176 B

__global__ void __launch_bounds__(512, 1)
conv_mma(const u32* __restrict__ pin,
         const u32* __restrict__ wA,
         const float* __restrict__ bias,
         const float* __restrict__ residual,
         float* __restrict__ out,
         int apply_leaky,
         const float* __restrict__ gcw,   // fused gate weights (or null)
         const float* __restrict__ gcb,
         float* __restrict__ Mout)
{
    extern __shared__ u32 dsm[];
    u32* wS[2] = { dsm, dsm + WCH };
    u32* iS[2] = { dsm + 2*WCH, dsm + 2*WCH + ICH };

    int tid = threadIdx.x;
    int wid = tid >> 5;
    int lane = tid & 31;
    int g = lane >> 2, tig = lane & 3;
    int wg = wid >> 2;                   // 0..3 -> row
    int warpbase = (wid & 3) * 32;
    int h0 = blockIdx.x * 4, b = blockIdx.z;
    int h = h0 + wg;

    // zero input buffers once (halo cols + off-image rows stay 0)
    for (int i = tid; i < 2*ICH; i += 512) dsm[2*WCH + i] = 0;

    u32 wS_a[2] = { smem_u32(wS[0]), smem_u32(wS[1]) };
    u32 iS_a[2] = { smem_u32(iS[0]), smem_u32(iS[1]) };
    __syncthreads();

    auto prefetch = [&](int chunk, int buf) {
        // weights: 2304 x 16B
        const u32* wsrc = wA + chunk * WCH;
#pragma unroll
        for (int i = 0; i < 5; i++) {
            int idx = tid + i*512;
            if (idx < 2304)
                cp_async16(wS_a[buf] + (u32)(idx*16), wsrc + idx*4);
        }
        // input: 16 ci x 6 rows x 32 segs = 3072 x 16B
#pragma unroll
        for (int i = 0; i < 6; i++) {
            int idx = tid + i*512;
            int ci  = idx / 192;
            int rem = idx - ci*192;
            int rr  = rem >> 5;          // 0..5
            int seg = rem & 31;
            int gy  = h0 - 1 + rr;
            if (gy >= 0 && gy < H_) {
                u32 dst = iS_a[buf] + (u32)(((ci*6 + rr)*RW2 + 4 + seg*4) * 4);
                cp_async16(dst, pin + (((size_t)b*C_ + chunk*16 + ci)*H_ + gy)*W_ + seg*4);
            }
        }
    };

    float D[4][4][4];
#pragma unroll
    for (int mt = 0; mt < 4; mt++)
#pragma unroll
        for (int nt = 0; nt < 4; nt++)
#pragma unroll
            for (int i = 0; i < 4; i++) D[mt][nt][i] = 0.f;

    prefetch(0, 0);
    cp_commit();

    for (int chunk = 0; chunk < 4; chunk++) {
        cp_wait_all();
        __syncthreads();

        if (chunk < 3) {
            prefetch(chunk + 1, (chunk + 1) & 1);
            cp_commit();
        }

        const u32* smW = wS[chunk & 1];
        const u32* inS = iS[chunk & 1];

#pragma unroll
        for (int s = 0; s < 9; s++) {
            uint4 Ah[4], Al[4];
#pragma unroll
            for (int mt = 0; mt < 4; mt++) {
                const u32* base = smW + ((s*4 + mt)*2)*128 + lane*4;
                Ah[mt] = *(const uint4*)(base);
                Al[mt] = *(const uint4*)(base + 128);
            }
#pragma unroll
            for (int nt = 0; nt < 4; nt++) {
                int n = warpbase + nt*8 + g;
                u32 bh[2], bl[2];
#pragma unroll
                for (int r = 0; r < 2; r++) {
                    int k0 = s*16 + 2*tig + r*8;
                    int k1 = k0 + 1;
                    int ci0 = k0/9, tap0 = k0 - ci0*9;
                    int ci1 = k1/9, tap1 = k1 - ci1*9;
                    u32 v0 = inS[(ci0*6 + wg + tap0/3)*RW2 + n + (tap0 % 3) + 3];
                    u32 v1 = inS[(ci1*6 + wg + tap1/3)*RW2 + n + (tap1 % 3) + 3];
                    bh[r] = __byte_perm(v0, v1, 0x7632);
                    bl[r] = __byte_perm(v0, v1, 0x5410);
                }
#pragma unroll
                for (int mt = 0; mt < 4; mt++) {
                    mma16816(D[mt][nt], (const u32*)&Ah[mt], bh[0], bh[1]);
                    mma16816(D[mt][nt], (const u32*)&Ah[mt], bl[0], bl[1]);
                    mma16816(D[mt][nt], (const u32*)&Al[mt], bh[0], bh[1]);
                }
            }
        }
    }

    // ---- epilogue (+ optional fused gate) ----
    float bv[4][2], cwv[4][2];
#pragma unroll
    for (int mt = 0; mt < 4; mt++) {
        int co0 = mt*16 + g;
        bv[mt][0] = bias[co0];
        bv[mt][1] = bias[co0 + 8];
        if (gcw) { cwv[mt][0] = gcw[co0]; cwv[mt][1] = gcw[co0 + 8]; }
    }
    float gb = gcw ? gcb[0] : 0.f;

#pragma unroll
    for (int nt = 0; nt < 4; nt++) {
        int px = warpbase + nt*8 + 2*tig;
        float gx = 0.f, gy = 0.f;
#pragma unroll
        for (int mt = 0; mt < 4; mt++) {
            int co0 = mt*16 + g;
            size_t o0 = (((size_t)b*C_ + co0    )*H_ + h)*W_ + px;
            size_t o1 = (((size_t)b*C_ + co0 + 8)*H_ + h)*W_ + px;
            float2 v0 = make_float2(D[mt][nt][0] + bv[mt][0], D[mt][nt][1] + bv[mt][0]);
            float2 v1 = make_float2(D[mt][nt][2] + bv[mt][1], D[mt][nt][3] + bv[mt][1]);
            if (apply_leaky) {
                v0.x = leaky01(v0.x); v0.y = leaky01(v0.y);
                v1.x = leaky01(v1.x); v1.y = leaky01(v1.y);
            }
            if (residual) {
                const float2 r0 = *(const float2*)&residual[o0];
                const float2 r1 = *(const float2*)&residual[o1];
                v0.x += r0.x; v0.y += r0.y; v1.x += r1.x; v1.y += r1.y;
            }
            *(float2*)&out[o0] = v0;
            *(float2*)&out[o1] = v1;
            if (gcw) {
                gx += v0.x*cwv[mt][0] + v1.x*cwv[mt][1];
                gy += v0.y*cwv[mt][0] + v1.y*cwv[mt][1];
            }
        }
        if (gcw) {
            // reduce over g-lanes (co groups): lanes differ in bits 2..4
#pragma unroll
            for (int ofs = 4; ofs <= 16; ofs <<= 1) {
                gx += __shfl_xor_sync(0xFFFFFFFFu, gx, ofs);
                gy += __shfl_xor_sync(0xFFFFFFFFu, gy, ofs);
            }
            if (g == 0) {
                float2 mo;
                mo.x = 1.f / (1.f + expf(-(gx + gb)));
                mo.y = 1.f / (1.f + expf(-(gy + gb)));
                *(float2*)&Mout[(size_t)b*HW_ + h*W_ + px] = mo;
            }
        }
    }
}

// ---------------------------------------------------------------------------
// launch
// ---------------------------------------------------------------------------
extern "C" void kernel_launch(void* const* d_in, const int* in_sizes, int n_in,
                              void* d_out, int out_size)
{
    const float* x       = (const float*)d_in[0];
    const float* d       = (const float*)d_in[1];
    const float* da1_k1  = (const float*)d_in[2];
    const float* da1_k2  = (const float*)d_in[3];
    const float* da1_cw  = (const float*)d_in[4];
    const float* da1_cb  = (const float*)d_in[5];
    const float* da2_k1  = (const float*)d_in[6];
    const float* da2_k2  = (const float*)d_in[7];
    const float* da2_cw  = (const float*)d_in[8];
    const float* da2_cb  = (const float*)d_in[9];
    const float* conv1_w = (const float*)d_in[10];
    const float* conv1_b = (const float*)d_in[11];
    const float* conv2_w = (const float*)d_in[12];
    const float* conv2_b = (const float*)d_in[13];
    float* out = (float*)d_out;

    u32 *buf1, *wa; float *buf2, *gate, *kern1, *kern2;
    cudaGetSymbolAddress((void**)&buf1,  g_buf1);
    cudaGetSymbolAddress((void**)&buf2,  g_buf2);
    cudaGetSymbolAddress((void**)&gate,  g_gate);
    cudaGetSymbolAddress((void**)&kern1, g_kern1);
    cudaGetSymbolAddress((void**)&kern2, g_kern2);
    cudaGetSymbolAddress((void**)&wa,    g_wA);

    cudaFuncSetAttribute(conv_mma, cudaFuncAttributeMaxDynamicSharedMemorySize, SMEM_DYN);

    mlp_kernel<<<dim3(B_, 2), 64>>>(d, da1_k1, da1_k2, da2_k1, da2_k2, kern1, kern2);
    wprep_kernel<<<(2*4*9*4*2*32*4 + 255)/256, 256>>>(conv1_w, conv2_w);

    gate_kernel<<<(B_*HW_/4)/256, 256>>>(x, da1_cw, da1_cb, gate);
    rda_kernel<<<dim3(HW_/4/256, C_, B_), 256>>>(x, kern1, gate, buf1);

    // conv1 + leaky, with fused gate2 (writes M for rda2 into `gate`)
    conv_mma<<<dim3(H_/4, 1, B_), 512, SMEM_DYN>>>(buf1, wa, conv1_b, nullptr,
                                                   buf2, 1, da2_cw, da2_cb, gate);

    rda_kernel<<<dim3(HW_/4/256, C_, B_), 256>>>(buf2, kern2, gate, buf1);

    // conv2 + residual(x)
    conv_mma<<<dim3(H_/4, 1, B_), 512, SMEM_DYN>>>(buf1, wa + 4*WCH, conv2_b, x,
                                                   out, 0, nullptr, nullptr, nullptr);
}

// round 13
// speedup vs baseline: 1.1376x; 1.1376x over previous
#include <cuda_runtime.h>
#include <cuda_bf16.h>
#include <math.h>

// ---------------------------------------------------------------------------
// RDAB block: x[16,64,128,128] fp32
// Round 13: R11 conv geometry (2 rows/block, 256 thr — no register spills)
// + gate2 fused into conv1 epilogue (butterfly shuffle over co-lanes).
// ---------------------------------------------------------------------------

#define B_   16
#define C_   64
#define H_   128
#define W_   128
#define HW_  (H_*W_)
#define CHW_ (C_*HW_)

typedef unsigned long long u64;
typedef unsigned int u32;
typedef unsigned short u16;

__device__ u32   g_buf1[(size_t)B_*CHW_];   // packed (bf16hi<<16)|bf16lo
__device__ float g_buf2[(size_t)B_*CHW_];
__device__ float g_gate[(size_t)B_*HW_];
__device__ float g_kern1[B_*C_*9];
__device__ float g_kern2[B_*C_*9];
// fragment-ordered weights: [conv2][chunk4][step9][mt4][half2][lane32][reg4] u32
__device__ u32   g_wA[2*4*9*4*2*32*4];

__device__ __forceinline__ float leaky01(float v) { return v > 0.f ? v : 0.1f*v; }

__device__ __forceinline__ u32 pack_hilo(float v) {
    __nv_bfloat16 h = __float2bfloat16(v);
    float vh = __bfloat162float(h);
    __nv_bfloat16 l = __float2bfloat16(v - vh);
    u16 hb = *reinterpret_cast<u16*>(&h);
    u16 lb = *reinterpret_cast<u16*>(&l);
    return ((u32)hb << 16) | (u32)lb;
}
__device__ __forceinline__ void mma16816(float* c, const u32* a, u32 b0, u32 b1) {
    asm volatile(
        "mma.sync.aligned.m16n8k16.row.col.f32.bf16.bf16.f32 "
        "{%0,%1,%2,%3}, {%4,%5,%6,%7}, {%8,%9}, {%0,%1,%2,%3};"
        : "+f"(c[0]), "+f"(c[1]), "+f"(c[2]), "+f"(c[3])
        : "r"(a[0]), "r"(a[1]), "r"(a[2]), "r"(a[3]), "r"(b0), "r"(b1));
}
__device__ __forceinline__ u32 smem_u32(const void* p) {
    u32 a;
    asm("{ .reg .u64 t; cvta.to.shared.u64 t, %1; cvt.u32.u64 %0, t; }"
        : "=r"(a) : "l"(p));
    return a;
}
__device__ __forceinline__ void cp_async16(u32 dst, const void* src) {
    asm volatile("cp.async.ca.shared.global [%0], [%1], 16;\n" :: "r"(dst), "l"(src));
}
__device__ __forceinline__ void cp_commit() { asm volatile("cp.async.commit_group;\n"); }
__device__ __forceinline__ void cp_wait_all() { asm volatile("cp.async.wait_group 0;\n"); }

// ---------------------------------------------------------------------------
// 1) dynamic-kernel MLP
// ---------------------------------------------------------------------------
__global__ void mlp_kernel(const float* __restrict__ d,
                           const float* __restrict__ k1a, const float* __restrict__ k2a,
                           const float* __restrict__ k1b, const float* __restrict__ k2b,
                           float* __restrict__ kern1, float* __restrict__ kern2)
{
    int b = blockIdx.x, stage = blockIdx.y;
    const float* k1 = stage ? k1b : k1a;
    const float* k2 = stage ? k2b : k2a;
    float* ko = stage ? kern2 : kern1;
    __shared__ float dd[64], hid[64];
    int t = threadIdx.x;
    dd[t] = d[b*64 + t];
    __syncthreads();
    float s = 0.f;
#pragma unroll 8
    for (int i = 0; i < 64; i++) s += dd[i] * k1[i*64 + t];
    hid[t] = leaky01(s);
    __syncthreads();
#pragma unroll
    for (int r = 0; r < 9; r++) {
        int o = r*64 + t;
        float s2 = 0.f;
#pragma unroll 8
        for (int i = 0; i < 64; i++) s2 += hid[i] * k2[i*576 + o];
        ko[b*576 + o] = s2;
    }
}

// ---------------------------------------------------------------------------
// 2) gating map from fp32 input (stage 1 only, reads x)
// ---------------------------------------------------------------------------
__global__ void gate_kernel(const float* __restrict__ in,
                            const float* __restrict__ cw,
                            const float* __restrict__ cb,
                            float* __restrict__ M)
{
    __shared__ float scw[C_];
    if (threadIdx.x < C_) scw[threadIdx.x] = cw[threadIdx.x];
    __syncthreads();
    int idx4 = blockIdx.x * blockDim.x + threadIdx.x;
    int b = idx4 / (HW_/4);
    int hw4 = idx4 - b * (HW_/4);
    const float* p = in + (size_t)b * CHW_ + hw4 * 4;
    float bias = cb[0];
    float4 s = make_float4(bias, bias, bias, bias);
#pragma unroll 8
    for (int c = 0; c < C_; c++) {
        float4 v = *(const float4*)(p + (size_t)c * HW_);
        float w = scw[c];
        s.x += w*v.x; s.y += w*v.y; s.z += w*v.z; s.w += w*v.w;
    }
    float4 r;
    r.x = 1.f/(1.f+expf(-s.x)); r.y = 1.f/(1.f+expf(-s.y));
    r.z = 1.f/(1.f+expf(-s.z)); r.w = 1.f/(1.f+expf(-s.w));
    *(float4*)&M[(size_t)b*HW_ + hw4*4] = r;
}

// ---------------------------------------------------------------------------
// 3) fused RDA, float4 — writes PACKED (bf16hi<<16|bf16lo)
// ---------------------------------------------------------------------------
__global__ void rda_kernel(const float* __restrict__ in,
                           const float* __restrict__ kern,
                           const float* __restrict__ M,
                           u32* __restrict__ outp)
{
    int idx4 = blockIdx.x * blockDim.x + threadIdx.x;
    int c = blockIdx.y, b = blockIdx.z;
    int h  = idx4 >> 5;
    int wq = (idx4 & 31) * 4;

    const float* k = kern + (b*C_ + c) * 9;
    float kk[9];
#pragma unroll
    for (int i = 0; i < 9; i++) kk[i] = k[i];

    const float* p = in + ((size_t)b*C_ + c) * HW_;
    float4 dw = make_float4(0.f, 0.f, 0.f, 0.f);
    float4 mid_c = *(const float4*)(p + h * W_ + wq);

#pragma unroll
    for (int r = 0; r < 3; r++) {
        int gy = h - 1 + r;
        if (gy < 0 || gy >= H_) continue;
        const float* rowp = p + gy * W_;
        float4 mid = (r == 1) ? mid_c : *(const float4*)(rowp + wq);
        float left  = (wq > 0)   ? rowp[wq - 1] : 0.f;
        float right = (wq < 124) ? rowp[wq + 4] : 0.f;
        float t0 = kk[r*3+0], t1 = kk[r*3+1], t2 = kk[r*3+2];
        dw.x += t0*left  + t1*mid.x + t2*mid.y;
        dw.y += t0*mid.x + t1*mid.y + t2*mid.z;
        dw.z += t0*mid.y + t1*mid.z + t2*mid.w;
        dw.w += t0*mid.z + t1*mid.w + t2*right;
    }

    float4 m = *(const float4*)&M[(size_t)b*HW_ + h*W_ + wq];
    uint4 o;
    o.x = pack_hilo(leaky01(leaky01(dw.x)*m.x + mid_c.x));
    o.y = pack_hilo(leaky01(leaky01(dw.y)*m.y + mid_c.y));
    o.z = pack_hilo(leaky01(leaky01(dw.z)*m.z + mid_c.z));
    o.w = pack_hilo(leaky01(leaky01(dw.w)*m.w + mid_c.w));
    *(uint4*)&outp[((size_t)b*C_ + c)*HW_ + h*W_ + wq] = o;
}

// ---------------------------------------------------------------------------
// 3b) weight prep: fp32 OIHW -> bf16 hi/lo in m16n8k16 A-fragment order.
// ---------------------------------------------------------------------------
__global__ void wprep_kernel(const float* __restrict__ w1,
                             const float* __restrict__ w2)
{
    int idx = blockIdx.x * blockDim.x + threadIdx.x;
    if (idx >= 2*4*9*4*2*32*4) return;
    int t = idx;
    int r    = t & 3;  t >>= 2;
    int lane = t & 31; t >>= 5;
    int q    = t & 1;  t >>= 1;
    int mt   = t & 3;  t >>= 2;
    int s9   = t % 9;  t /= 9;
    int chunk= t & 3;  t >>= 2;
    int s2   = t;

    int g = lane >> 2, tig = lane & 3;
    int co = mt*16 + g + (r & 1)*8;
    int k0 = s9*16 + 2*tig + (r >> 1)*8;
    int k1 = k0 + 1;

    const float* w = s2 ? w2 : w1;
    int ci0 = k0/9, tap0 = k0 - ci0*9;
    int ci1 = k1/9, tap1 = k1 - ci1*9;
    float w0 = w[(co*C_ + chunk*16 + ci0)*9 + tap0];
    float w1v= w[(co*C_ + chunk*16 + ci1)*9 + tap1];

    u16 p0, p1;
    if (q == 0) {
        __nv_bfloat16 h0 = __float2bfloat16(w0), h1 = __float2bfloat16(w1v);
        p0 = *reinterpret_cast<u16*>(&h0); p1 = *reinterpret_cast<u16*>(&h1);
    } else {
        __nv_bfloat16 h0 = __float2bfloat16(w0);
        __nv_bfloat16 l0 = __float2bfloat16(w0 - __bfloat162float(h0));
        __nv_bfloat16 h1 = __float2bfloat16(w1v);
        __nv_bfloat16 l1 = __float2bfloat16(w1v - __bfloat162float(h1));
        p0 = *reinterpret_cast<u16*>(&l0); p1 = *reinterpret_cast<u16*>(&l1);
    }
    g_wA[idx] = ((u32)p1 << 16) | (u32)p0;
}

// ---------------------------------------------------------------------------
// 4) mma.sync conv (R11 geometry): block = 2 rows, 256 threads = 8 warps.
//    wg = wid>>2 handles row h0+wg; warp (wid&3) covers 32 px, all 64 co.
//    cp.async double-buffered weights + input. Optional fused gate epilogue.
// ---------------------------------------------------------------------------
#define RW2  136
#define WCH  9216                       // u32 per weight chunk
#define ICH  (16*4*RW2)                 // 8704 u32 per input chunk
#define SMEM_DYN ((2*WCH + 2*ICH) * 4)  // 143360 B

__global__ void __launch_bounds__(256, 1)
conv_mma(const u32* __restrict__ pin,
         const u32* __restrict__ wA,
         const float* __restrict__ bias,
         const float* __restrict__ residual,
         float* __restrict__ out,
         int apply_leaky,
         const float* __restrict__ gcw,   // fused gate weights (or null)
         const float* __restrict__ gcb,
         float* __restrict__ Mout)
{
    extern __shared__ u32 dsm[];
    u32* wS[2] = { dsm, dsm + WCH };
    u32* iS[2] = { dsm + 2*WCH, dsm + 2*WCH + ICH };

    int tid = threadIdx.x;
    int wid = tid >> 5;
    int lane = tid & 31;
    int g = lane >> 2, tig = lane & 3;
    int wg = wid >> 2;                   // row group 0/1
    int warpbase = (wid & 3) * 32;
    int h0 = blockIdx.x * 2, b = blockIdx.z;
    int h = h0 + wg;

    // zero input buffers once (halo cols + off-image rows stay 0)
    for (int i = tid; i < 2*ICH; i += 256) dsm[2*WCH + i] = 0;

    u32 wS_a[2] = { smem_u32(wS[0]), smem_u32(wS[1]) };
    u32 iS_a[2] = { smem_u32(iS[0]), smem_u32(iS[1]) };
    __syncthreads();

    auto prefetch = [&](int chunk, int buf) {
        const u32* wsrc = wA + chunk * WCH;
#pragma unroll
        for (int i = 0; i < 9; i++) {
            int idx = tid + i*256;                 // 0..2303
            cp_async16(wS_a[buf] + (u32)(idx*16), wsrc + idx*4);
        }
#pragma unroll
        for (int i = 0; i < 8; i++) {
            int idx = tid + i*256;
            int ci  = idx >> 7;
            int rr  = (idx >> 5) & 3;
            int seg = idx & 31;
            int gy  = h0 - 1 + rr;
            if (gy >= 0 && gy < H_) {
                u32 dst = iS_a[buf] + (u32)(((ci*4 + rr)*RW2 + 4 + seg*4) * 4);
                cp_async16(dst, pin + (((size_t)b*C_ + chunk*16 + ci)*H_ + gy)*W_ + seg*4);
            }
        }
    };

    float D[4][4][4];
#pragma unroll
    for (int mt = 0; mt < 4; mt++)
#pragma unroll
        for (int nt = 0; nt < 4; nt++)
#pragma unroll
            for (int i = 0; i < 4; i++) D[mt][nt][i] = 0.f;

    prefetch(0, 0);
    cp_commit();

    for (int chunk = 0; chunk < 4; chunk++) {
        cp_wait_all();
        __syncthreads();

        if (chunk < 3) {
            prefetch(chunk + 1, (chunk + 1) & 1);
            cp_commit();
        }

        const u32* smW = wS[chunk & 1];
        const u32* inS = iS[chunk & 1];

#pragma unroll
        for (int s = 0; s < 9; s++) {
            uint4 Ah[4], Al[4];
#pragma unroll
            for (int mt = 0; mt < 4; mt++) {
                const u32* base = smW + ((s*4 + mt)*2)*128 + lane*4;
                Ah[mt] = *(const uint4*)(base);
                Al[mt] = *(const uint4*)(base + 128);
            }
#pragma unroll
            for (int nt = 0; nt < 4; nt++) {
                int n = warpbase + nt*8 + g;
                u32 bh[2], bl[2];
#pragma unroll
                for (int r = 0; r < 2; r++) {
                    int k0 = s*16 + 2*tig + r*8;
                    int k1 = k0 + 1;
                    int ci0 = k0/9, tap0 = k0 - ci0*9;
                    int ci1 = k1/9, tap1 = k1 - ci1*9;
                    u32 v0 = inS[(ci0*4 + wg + tap0/3)*RW2 + n + (tap0 % 3) + 3];
                    u32 v1 = inS[(ci1*4 + wg + tap1/3)*RW2 + n + (tap1 % 3) + 3];
                    bh[r] = __byte_perm(v0, v1, 0x7632);
                    bl[r] = __byte_perm(v0, v1, 0x5410);
                }
#pragma unroll
                for (int mt = 0; mt < 4; mt++) {
                    mma16816(D[mt][nt], (const u32*)&Ah[mt], bh[0], bh[1]);
                    mma16816(D[mt][nt], (const u32*)&Ah[mt], bl[0], bl[1]);
                    mma16816(D[mt][nt], (const u32*)&Al[mt], bh[0], bh[1]);
                }
            }
        }
    }

    // ---- epilogue (+ optional fused gate) ----
    float bv[4][2], cwv[4][2];
#pragma unroll
    for (int mt = 0; mt < 4; mt++) {
        int co0 = mt*16 + g;
        bv[mt][0] = bias[co0];
        bv[mt][1] = bias[co0 + 8];
        if (gcw) { cwv[mt][0] = gcw[co0]; cwv[mt][1] = gcw[co0 + 8]; }
    }
    float gb = gcw ? gcb[0] : 0.f;

#pragma unroll
    for (int nt = 0; nt < 4; nt++) {
        int px = warpbase + nt*8 + 2*tig;
        float gx = 0.f, gy = 0.f;
#pragma unroll
        for (int mt = 0; mt < 4; mt++) {
            int co0 = mt*16 + g;
            size_t o0 = (((size_t)b*C_ + co0    )*H_ + h)*W_ + px;
            size_t o1 = (((size_t)b*C_ + co0 + 8)*H_ + h)*W_ + px;
            float2 v0 = make_float2(D[mt][nt][0] + bv[mt][0], D[mt][nt][1] + bv[mt][0]);
            float2 v1 = make_float2(D[mt][nt][2] + bv[mt][1], D[mt][nt][3] + bv[mt][1]);
            if (apply_leaky) {
                v0.x = leaky01(v0.x); v0.y = leaky01(v0.y);
                v1.x = leaky01(v1.x); v1.y = leaky01(v1.y);
            }
            if (residual) {
                const float2 r0 = *(const float2*)&residual[o0];
                const float2 r1 = *(const float2*)&residual[o1];
                v0.x += r0.x; v0.y += r0.y; v1.x += r1.x; v1.y += r1.y;
            }
            *(float2*)&out[o0] = v0;
            *(float2*)&out[o1] = v1;
            if (gcw) {
                gx += v0.x*cwv[mt][0] + v1.x*cwv[mt][1];
                gy += v0.y*cwv[mt][0] + v1.y*cwv[mt][1];
            }
        }
        if (gcw) {
            // reduce over g-lanes (co groups): lanes differ in bits 2..4
#pragma unroll
            for (int ofs = 4; ofs <= 16; ofs <<= 1) {
                gx += __shfl_xor_sync(0xFFFFFFFFu, gx, ofs);
                gy += __shfl_xor_sync(0xFFFFFFFFu, gy, ofs);
            }
            if (g == 0) {
                float2 mo;
                mo.x = 1.f / (1.f + expf(-(gx + gb)));
                mo.y = 1.f / (1.f + expf(-(gy + gb)));
                *(float2*)&Mout[(size_t)b*HW_ + h*W_ + px] = mo;
            }
        }
    }
}

// ---------------------------------------------------------------------------
// launch
// ---------------------------------------------------------------------------
extern "C" void kernel_launch(void* const* d_in, const int* in_sizes, int n_in,
                              void* d_out, int out_size)
{
    const float* x       = (const float*)d_in[0];
    const float* d       = (const float*)d_in[1];
    const float* da1_k1  = (const float*)d_in[2];
    const float* da1_k2  = (const float*)d_in[3];
    const float* da1_cw  = (const float*)d_in[4];
    const float* da1_cb  = (const float*)d_in[5];
    const float* da2_k1  = (const float*)d_in[6];
    const float* da2_k2  = (const float*)d_in[7];
    const float* da2_cw  = (const float*)d_in[8];
    const float* da2_cb  = (const float*)d_in[9];
    const float* conv1_w = (const float*)d_in[10];
    const float* conv1_b = (const float*)d_in[11];
    const float* conv2_w = (const float*)d_in[12];
    const float* conv2_b = (const float*)d_in[13];
    float* out = (float*)d_out;

    u32 *buf1, *wa; float *buf2, *gate, *kern1, *kern2;
    cudaGetSymbolAddress((void**)&buf1,  g_buf1);
    cudaGetSymbolAddress((void**)&buf2,  g_buf2);
    cudaGetSymbolAddress((void**)&gate,  g_gate);
    cudaGetSymbolAddress((void**)&kern1, g_kern1);
    cudaGetSymbolAddress((void**)&kern2, g_kern2);
    cudaGetSymbolAddress((void**)&wa,    g_wA);

    cudaFuncSetAttribute(conv_mma, cudaFuncAttributeMaxDynamicSharedMemorySize, SMEM_DYN);

    mlp_kernel<<<dim3(B_, 2), 64>>>(d, da1_k1, da1_k2, da2_k1, da2_k2, kern1, kern2);
    wprep_kernel<<<(2*4*9*4*2*32*4 + 255)/256, 256>>>(conv1_w, conv2_w);

    gate_kernel<<<(B_*HW_/4)/256, 256>>>(x, da1_cw, da1_cb, gate);
    rda_kernel<<<dim3(HW_/4/256, C_, B_), 256>>>(x, kern1, gate, buf1);

    // conv1 + leaky, with fused gate2 (writes M for rda2 into `gate`)
    conv_mma<<<dim3(H_/2, 1, B_), 256, SMEM_DYN>>>(buf1, wa, conv1_b, nullptr,
                                                   buf2, 1, da2_cw, da2_cb, gate);

    rda_kernel<<<dim3(HW_/4/256, C_, B_), 256>>>(buf2, kern2, gate, buf1);

    // conv2 + residual(x)
    conv_mma<<<dim3(H_/2, 1, B_), 256, SMEM_DYN>>>(buf1, wa + 4*WCH, conv2_b, x,
                                                   out, 0, nullptr, nullptr, nullptr);
}

// round 14
// speedup vs baseline: 1.1785x; 1.0360x over previous
#include <cuda_runtime.h>
#include <cuda_bf16.h>
#include <math.h>

// ---------------------------------------------------------------------------
// RDAB block: x[16,64,128,128] fp32
// Round 14: mma.sync conv, occupancy edition:
//   - 1 row/block, warp = 64co x 16px (nt=2) -> ~110 regs -> 2 CTAs/SM
//   - weights via direct LDG.128 (L1-resident), smem only for input
//   - gate2 stays fused in conv1 epilogue
// ---------------------------------------------------------------------------

#define B_   16
#define C_   64
#define H_   128
#define W_   128
#define HW_  (H_*W_)
#define CHW_ (C_*HW_)

typedef unsigned long long u64;
typedef unsigned int u32;
typedef unsigned short u16;

__device__ u32   g_buf1[(size_t)B_*CHW_];   // packed (bf16hi<<16)|bf16lo
__device__ float g_buf2[(size_t)B_*CHW_];
__device__ float g_gate[(size_t)B_*HW_];
__device__ float g_kern1[B_*C_*9];
__device__ float g_kern2[B_*C_*9];
// fragment-ordered weights: [conv2][chunk4][step9][mt4][half2][lane32][reg4] u32
__device__ u32   g_wA[2*4*9*4*2*32*4];

__device__ __forceinline__ float leaky01(float v) { return v > 0.f ? v : 0.1f*v; }

__device__ __forceinline__ u32 pack_hilo(float v) {
    __nv_bfloat16 h = __float2bfloat16(v);
    float vh = __bfloat162float(h);
    __nv_bfloat16 l = __float2bfloat16(v - vh);
    u16 hb = *reinterpret_cast<u16*>(&h);
    u16 lb = *reinterpret_cast<u16*>(&l);
    return ((u32)hb << 16) | (u32)lb;
}
__device__ __forceinline__ void mma16816(float* c, const u32* a, u32 b0, u32 b1) {
    asm volatile(
        "mma.sync.aligned.m16n8k16.row.col.f32.bf16.bf16.f32 "
        "{%0,%1,%2,%3}, {%4,%5,%6,%7}, {%8,%9}, {%0,%1,%2,%3};"
        : "+f"(c[0]), "+f"(c[1]), "+f"(c[2]), "+f"(c[3])
        : "r"(a[0]), "r"(a[1]), "r"(a[2]), "r"(a[3]), "r"(b0), "r"(b1));
}
__device__ __forceinline__ u32 smem_u32(const void* p) {
    u32 a;
    asm("{ .reg .u64 t; cvta.to.shared.u64 t, %1; cvt.u32.u64 %0, t; }"
        : "=r"(a) : "l"(p));
    return a;
}
__device__ __forceinline__ void cp_async16(u32 dst, const void* src) {
    asm volatile("cp.async.ca.shared.global [%0], [%1], 16;\n" :: "r"(dst), "l"(src));
}
__device__ __forceinline__ void cp_commit() { asm volatile("cp.async.commit_group;\n"); }
__device__ __forceinline__ void cp_wait_all() { asm volatile("cp.async.wait_group 0;\n"); }

// ---------------------------------------------------------------------------
// 1) dynamic-kernel MLP
// ---------------------------------------------------------------------------
__global__ void mlp_kernel(const float* __restrict__ d,
                           const float* __restrict__ k1a, const float* __restrict__ k2a,
                           const float* __restrict__ k1b, const float* __restrict__ k2b,
                           float* __restrict__ kern1, float* __restrict__ kern2)
{
    int b = blockIdx.x, stage = blockIdx.y;
    const float* k1 = stage ? k1b : k1a;
    const float* k2 = stage ? k2b : k2a;
    float* ko = stage ? kern2 : kern1;
    __shared__ float dd[64], hid[64];
    int t = threadIdx.x;
    dd[t] = d[b*64 + t];
    __syncthreads();
    float s = 0.f;
#pragma unroll 8
    for (int i = 0; i < 64; i++) s += dd[i] * k1[i*64 + t];
    hid[t] = leaky01(s);
    __syncthreads();
#pragma unroll
    for (int r = 0; r < 9; r++) {
        int o = r*64 + t;
        float s2 = 0.f;
#pragma unroll 8
        for (int i = 0; i < 64; i++) s2 += hid[i] * k2[i*576 + o];
        ko[b*576 + o] = s2;
    }
}

// ---------------------------------------------------------------------------
// 2) gating map from fp32 input (stage 1 only, reads x)
// ---------------------------------------------------------------------------
__global__ void gate_kernel(const float* __restrict__ in,
                            const float* __restrict__ cw,
                            const float* __restrict__ cb,
                            float* __restrict__ M)
{
    __shared__ float scw[C_];
    if (threadIdx.x < C_) scw[threadIdx.x] = cw[threadIdx.x];
    __syncthreads();
    int idx4 = blockIdx.x * blockDim.x + threadIdx.x;
    int b = idx4 / (HW_/4);
    int hw4 = idx4 - b * (HW_/4);
    const float* p = in + (size_t)b * CHW_ + hw4 * 4;
    float bias = cb[0];
    float4 s = make_float4(bias, bias, bias, bias);
#pragma unroll 8
    for (int c = 0; c < C_; c++) {
        float4 v = *(const float4*)(p + (size_t)c * HW_);
        float w = scw[c];
        s.x += w*v.x; s.y += w*v.y; s.z += w*v.z; s.w += w*v.w;
    }
    float4 r;
    r.x = 1.f/(1.f+expf(-s.x)); r.y = 1.f/(1.f+expf(-s.y));
    r.z = 1.f/(1.f+expf(-s.z)); r.w = 1.f/(1.f+expf(-s.w));
    *(float4*)&M[(size_t)b*HW_ + hw4*4] = r;
}

// ---------------------------------------------------------------------------
// 3) fused RDA, float4 — writes PACKED (bf16hi<<16|bf16lo)
// ---------------------------------------------------------------------------
__global__ void rda_kernel(const float* __restrict__ in,
                           const float* __restrict__ kern,
                           const float* __restrict__ M,
                           u32* __restrict__ outp)
{
    int idx4 = blockIdx.x * blockDim.x + threadIdx.x;
    int c = blockIdx.y, b = blockIdx.z;
    int h  = idx4 >> 5;
    int wq = (idx4 & 31) * 4;

    const float* k = kern + (b*C_ + c) * 9;
    float kk[9];
#pragma unroll
    for (int i = 0; i < 9; i++) kk[i] = k[i];

    const float* p = in + ((size_t)b*C_ + c) * HW_;
    float4 dw = make_float4(0.f, 0.f, 0.f, 0.f);
    float4 mid_c = *(const float4*)(p + h * W_ + wq);

#pragma unroll
    for (int r = 0; r < 3; r++) {
        int gy = h - 1 + r;
        if (gy < 0 || gy >= H_) continue;
        const float* rowp = p + gy * W_;
        float4 mid = (r == 1) ? mid_c : *(const float4*)(rowp + wq);
        float left  = (wq > 0)   ? rowp[wq - 1] : 0.f;
        float right = (wq < 124) ? rowp[wq + 4] : 0.f;
        float t0 = kk[r*3+0], t1 = kk[r*3+1], t2 = kk[r*3+2];
        dw.x += t0*left  + t1*mid.x + t2*mid.y;
        dw.y += t0*mid.x + t1*mid.y + t2*mid.z;
        dw.z += t0*mid.y + t1*mid.z + t2*mid.w;
        dw.w += t0*mid.z + t1*mid.w + t2*right;
    }

    float4 m = *(const float4*)&M[(size_t)b*HW_ + h*W_ + wq];
    uint4 o;
    o.x = pack_hilo(leaky01(leaky01(dw.x)*m.x + mid_c.x));
    o.y = pack_hilo(leaky01(leaky01(dw.y)*m.y + mid_c.y));
    o.z = pack_hilo(leaky01(leaky01(dw.z)*m.z + mid_c.z));
    o.w = pack_hilo(leaky01(leaky01(dw.w)*m.w + mid_c.w));
    *(uint4*)&outp[((size_t)b*C_ + c)*HW_ + h*W_ + wq] = o;
}

// ---------------------------------------------------------------------------
// 3b) weight prep: fp32 OIHW -> bf16 hi/lo in m16n8k16 A-fragment order.
// ---------------------------------------------------------------------------
__global__ void wprep_kernel(const float* __restrict__ w1,
                             const float* __restrict__ w2)
{
    int idx = blockIdx.x * blockDim.x + threadIdx.x;
    if (idx >= 2*4*9*4*2*32*4) return;
    int t = idx;
    int r    = t & 3;  t >>= 2;
    int lane = t & 31; t >>= 5;
    int q    = t & 1;  t >>= 1;
    int mt   = t & 3;  t >>= 2;
    int s9   = t % 9;  t /= 9;
    int chunk= t & 3;  t >>= 2;
    int s2   = t;

    int g = lane >> 2, tig = lane & 3;
    int co = mt*16 + g + (r & 1)*8;
    int k0 = s9*16 + 2*tig + (r >> 1)*8;
    int k1 = k0 + 1;

    const float* w = s2 ? w2 : w1;
    int ci0 = k0/9, tap0 = k0 - ci0*9;
    int ci1 = k1/9, tap1 = k1 - ci1*9;
    float w0 = w[(co*C_ + chunk*16 + ci0)*9 + tap0];
    float w1v= w[(co*C_ + chunk*16 + ci1)*9 + tap1];

    u16 p0, p1;
    if (q == 0) {
        __nv_bfloat16 h0 = __float2bfloat16(w0), h1 = __float2bfloat16(w1v);
        p0 = *reinterpret_cast<u16*>(&h0); p1 = *reinterpret_cast<u16*>(&h1);
    } else {
        __nv_bfloat16 h0 = __float2bfloat16(w0);
        __nv_bfloat16 l0 = __float2bfloat16(w0 - __bfloat162float(h0));
        __nv_bfloat16 h1 = __float2bfloat16(w1v);
        __nv_bfloat16 l1 = __float2bfloat16(w1v - __bfloat162float(h1));
        p0 = *reinterpret_cast<u16*>(&l0); p1 = *reinterpret_cast<u16*>(&l1);
    }
    g_wA[idx] = ((u32)p1 << 16) | (u32)p0;
}

// ---------------------------------------------------------------------------
// 4) mma.sync conv v4: block = 1 row, 256 threads = 8 warps.
//    Warp wid covers px [wid*16, wid*16+16) (nt=2), all 64 co (mt=4).
//    Input: cp.async double-buffered 16ci x 3rows x RW2. Weights: LDG.128
//    (uniform across warps, L1-resident). ~110 regs -> 2 CTAs/SM.
// ---------------------------------------------------------------------------
#define RW2  136
#define WCH  9216                        // u32 per fragment-weight chunk
#define ICH3 (16*3*RW2)                  // 6528 u32 per input chunk
#define SMEM_DYN (2*ICH3*4)              // 52224 B

__global__ void __launch_bounds__(256, 2)
conv_mma(const u32* __restrict__ pin,
         const u32* __restrict__ wA,
         const float* __restrict__ bias,
         const float* __restrict__ residual,
         float* __restrict__ out,
         int apply_leaky,
         const float* __restrict__ gcw,   // fused gate weights (or null)
         const float* __restrict__ gcb,
         float* __restrict__ Mout)
{
    extern __shared__ u32 dsm[];
    u32* iS[2] = { dsm, dsm + ICH3 };

    int tid = threadIdx.x;
    int wid = tid >> 5;
    int lane = tid & 31;
    int g = lane >> 2, tig = lane & 3;
    int warpbase = wid * 16;
    int h = blockIdx.x, b = blockIdx.z;

    // zero input buffers once (halo cols + off-image rows stay 0)
    for (int i = tid; i < 2*ICH3; i += 256) dsm[i] = 0;

    u32 iS_a[2] = { smem_u32(iS[0]), smem_u32(iS[1]) };
    __syncthreads();

    // prefetch input chunk: 16 ci x 3 rows x 32 segs = 1536 x 16B
    auto prefetch = [&](int chunk, int buf) {
#pragma unroll
        for (int i = 0; i < 6; i++) {
            int idx = tid + i*256;               // 0..1535
            int ci  = idx / 96;
            int rem = idx - ci*96;
            int rr  = rem >> 5;                  // 0..2
            int seg = rem & 31;
            int gy  = h - 1 + rr;
            if (gy >= 0 && gy < H_) {
                u32 dst = iS_a[buf] + (u32)(((ci*3 + rr)*RW2 + 4 + seg*4) * 4);
                cp_async16(dst, pin + (((size_t)b*C_ + chunk*16 + ci)*H_ + gy)*W_ + seg*4);
            }
        }
    };

    float D[4][2][4];
#pragma unroll
    for (int mt = 0; mt < 4; mt++)
#pragma unroll
        for (int nt = 0; nt < 2; nt++)
#pragma unroll
            for (int i = 0; i < 4; i++) D[mt][nt][i] = 0.f;

    prefetch(0, 0);
    cp_commit();

    for (int chunk = 0; chunk < 4; chunk++) {
        cp_wait_all();
        __syncthreads();

        if (chunk < 3) {
            prefetch(chunk + 1, (chunk + 1) & 1);
            cp_commit();
        }

        const u32* inS = iS[chunk & 1];
        const u32* wc  = wA + chunk * WCH;

#pragma unroll
        for (int s = 0; s < 9; s++) {
            uint4 Ah[4], Al[4];
#pragma unroll
            for (int mt = 0; mt < 4; mt++) {
                const uint4* base = (const uint4*)(wc + ((s*4 + mt)*2)*128 + lane*4);
                Ah[mt] = __ldg(base);
                Al[mt] = __ldg(base + 32);       // +128 u32 = +32 uint4
            }
#pragma unroll
            for (int nt = 0; nt < 2; nt++) {
                int n = warpbase + nt*8 + g;
                u32 bh[2], bl[2];
#pragma unroll
                for (int r = 0; r < 2; r++) {
                    int k0 = s*16 + 2*tig + r*8;
                    int k1 = k0 + 1;
                    int ci0 = k0/9, tap0 = k0 - ci0*9;
                    int ci1 = k1/9, tap1 = k1 - ci1*9;
                    u32 v0 = inS[(ci0*3 + tap0/3)*RW2 + n + (tap0 % 3) + 3];
                    u32 v1 = inS[(ci1*3 + tap1/3)*RW2 + n + (tap1 % 3) + 3];
                    bh[r] = __byte_perm(v0, v1, 0x7632);
                    bl[r] = __byte_perm(v0, v1, 0x5410);
                }
#pragma unroll
                for (int mt = 0; mt < 4; mt++) {
                    mma16816(D[mt][nt], (const u32*)&Ah[mt], bh[0], bh[1]);
                    mma16816(D[mt][nt], (const u32*)&Ah[mt], bl[0], bl[1]);
                    mma16816(D[mt][nt], (const u32*)&Al[mt], bh[0], bh[1]);
                }
            }
        }
    }

    // ---- epilogue (+ optional fused gate) ----
    float bv[4][2], cwv[4][2];
#pragma unroll
    for (int mt = 0; mt < 4; mt++) {
        int co0 = mt*16 + g;
        bv[mt][0] = bias[co0];
        bv[mt][1] = bias[co0 + 8];
        if (gcw) { cwv[mt][0] = gcw[co0]; cwv[mt][1] = gcw[co0 + 8]; }
    }
    float gb = gcw ? gcb[0] : 0.f;

#pragma unroll
    for (int nt = 0; nt < 2; nt++) {
        int px = warpbase + nt*8 + 2*tig;
        float gx = 0.f, gy = 0.f;
#pragma unroll
        for (int mt = 0; mt < 4; mt++) {
            int co0 = mt*16 + g;
            size_t o0 = (((size_t)b*C_ + co0    )*H_ + h)*W_ + px;
            size_t o1 = (((size_t)b*C_ + co0 + 8)*H_ + h)*W_ + px;
            float2 v0 = make_float2(D[mt][nt][0] + bv[mt][0], D[mt][nt][1] + bv[mt][0]);
            float2 v1 = make_float2(D[mt][nt][2] + bv[mt][1], D[mt][nt][3] + bv[mt][1]);
            if (apply_leaky) {
                v0.x = leaky01(v0.x); v0.y = leaky01(v0.y);
                v1.x = leaky01(v1.x); v1.y = leaky01(v1.y);
            }
            if (residual) {
                const float2 r0 = *(const float2*)&residual[o0];
                const float2 r1 = *(const float2*)&residual[o1];
                v0.x += r0.x; v0.y += r0.y; v1.x += r1.x; v1.y += r1.y;
            }
            *(float2*)&out[o0] = v0;
            *(float2*)&out[o1] = v1;
            if (gcw) {
                gx += v0.x*cwv[mt][0] + v1.x*cwv[mt][1];
                gy += v0.y*cwv[mt][0] + v1.y*cwv[mt][1];
            }
        }
        if (gcw) {
            // reduce over g-lanes (co groups): lanes differ in bits 2..4
#pragma unroll
            for (int ofs = 4; ofs <= 16; ofs <<= 1) {
                gx += __shfl_xor_sync(0xFFFFFFFFu, gx, ofs);
                gy += __shfl_xor_sync(0xFFFFFFFFu, gy, ofs);
            }
            if (g == 0) {
                float2 mo;
                mo.x = 1.f / (1.f + expf(-(gx + gb)));
                mo.y = 1.f / (1.f + expf(-(gy + gb)));
                *(float2*)&Mout[(size_t)b*HW_ + h*W_ + px] = mo;
            }
        }
    }
}

// ---------------------------------------------------------------------------
// launch
// ---------------------------------------------------------------------------
extern "C" void kernel_launch(void* const* d_in, const int* in_sizes, int n_in,
                              void* d_out, int out_size)
{
    const float* x       = (const float*)d_in[0];
    const float* d       = (const float*)d_in[1];
    const float* da1_k1  = (const float*)d_in[2];
    const float* da1_k2  = (const float*)d_in[3];
    const float* da1_cw  = (const float*)d_in[4];
    const float* da1_cb  = (const float*)d_in[5];
    const float* da2_k1  = (const float*)d_in[6];
    const float* da2_k2  = (const float*)d_in[7];
    const float* da2_cw  = (const float*)d_in[8];
    const float* da2_cb  = (const float*)d_in[9];
    const float* conv1_w = (const float*)d_in[10];
    const float* conv1_b = (const float*)d_in[11];
    const float* conv2_w = (const float*)d_in[12];
    const float* conv2_b = (const float*)d_in[13];
    float* out = (float*)d_out;

    u32 *buf1, *wa; float *buf2, *gate, *kern1, *kern2;
    cudaGetSymbolAddress((void**)&buf1,  g_buf1);
    cudaGetSymbolAddress((void**)&buf2,  g_buf2);
    cudaGetSymbolAddress((void**)&gate,  g_gate);
    cudaGetSymbolAddress((void**)&kern1, g_kern1);
    cudaGetSymbolAddress((void**)&kern2, g_kern2);
    cudaGetSymbolAddress((void**)&wa,    g_wA);

    cudaFuncSetAttribute(conv_mma, cudaFuncAttributeMaxDynamicSharedMemorySize, SMEM_DYN);

    mlp_kernel<<<dim3(B_, 2), 64>>>(d, da1_k1, da1_k2, da2_k1, da2_k2, kern1, kern2);
    wprep_kernel<<<(2*4*9*4*2*32*4 + 255)/256, 256>>>(conv1_w, conv2_w);

    gate_kernel<<<(B_*HW_/4)/256, 256>>>(x, da1_cw, da1_cb, gate);
    rda_kernel<<<dim3(HW_/4/256, C_, B_), 256>>>(x, kern1, gate, buf1);

    // conv1 + leaky, with fused gate2 (writes M for rda2 into `gate`)
    conv_mma<<<dim3(H_, 1, B_), 256, SMEM_DYN>>>(buf1, wa, conv1_b, nullptr,
                                                 buf2, 1, da2_cw, da2_cb, gate);

    rda_kernel<<<dim3(HW_/4/256, C_, B_), 256>>>(buf2, kern2, gate, buf1);

    // conv2 + residual(x)
    conv_mma<<<dim3(H_, 1, B_), 256, SMEM_DYN>>>(buf1, wa + 4*WCH, conv2_b, x,
                                                 out, 0, nullptr, nullptr, nullptr);
}

// round 15
// speedup vs baseline: 1.2577x; 1.0672x over previous
#include <cuda_runtime.h>
#include <cuda_bf16.h>
#include <math.h>

// ---------------------------------------------------------------------------
// RDAB block: x[16,64,128,128] fp32
// Round 15: mma.sync conv — 128 thr/block, nt=4, launch_bounds(128,2):
//   256-reg budget (no spills), 2 CTA/SM (8 warps), halved weight-load
//   issues per MMA. Input cp.async double-buffered; gate2 fused in conv1.
// ---------------------------------------------------------------------------

#define B_   16
#define C_   64
#define H_   128
#define W_   128
#define HW_  (H_*W_)
#define CHW_ (C_*HW_)

typedef unsigned long long u64;
typedef unsigned int u32;
typedef unsigned short u16;

__device__ u32   g_buf1[(size_t)B_*CHW_];   // packed (bf16hi<<16)|bf16lo
__device__ float g_buf2[(size_t)B_*CHW_];
__device__ float g_gate[(size_t)B_*HW_];
__device__ float g_kern1[B_*C_*9];
__device__ float g_kern2[B_*C_*9];
// fragment-ordered weights: [conv2][chunk4][step9][mt4][half2][lane32][reg4] u32
__device__ u32   g_wA[2*4*9*4*2*32*4];

__device__ __forceinline__ float leaky01(float v) { return v > 0.f ? v : 0.1f*v; }

__device__ __forceinline__ u32 pack_hilo(float v) {
    __nv_bfloat16 h = __float2bfloat16(v);
    float vh = __bfloat162float(h);
    __nv_bfloat16 l = __float2bfloat16(v - vh);
    u16 hb = *reinterpret_cast<u16*>(&h);
    u16 lb = *reinterpret_cast<u16*>(&l);
    return ((u32)hb << 16) | (u32)lb;
}
__device__ __forceinline__ void mma16816(float* c, const u32* a, u32 b0, u32 b1) {
    asm volatile(
        "mma.sync.aligned.m16n8k16.row.col.f32.bf16.bf16.f32 "
        "{%0,%1,%2,%3}, {%4,%5,%6,%7}, {%8,%9}, {%0,%1,%2,%3};"
        : "+f"(c[0]), "+f"(c[1]), "+f"(c[2]), "+f"(c[3])
        : "r"(a[0]), "r"(a[1]), "r"(a[2]), "r"(a[3]), "r"(b0), "r"(b1));
}
__device__ __forceinline__ u32 smem_u32(const void* p) {
    u32 a;
    asm("{ .reg .u64 t; cvta.to.shared.u64 t, %1; cvt.u32.u64 %0, t; }"
        : "=r"(a) : "l"(p));
    return a;
}
__device__ __forceinline__ void cp_async16(u32 dst, const void* src) {
    asm volatile("cp.async.ca.shared.global [%0], [%1], 16;\n" :: "r"(dst), "l"(src));
}
__device__ __forceinline__ void cp_commit() { asm volatile("cp.async.commit_group;\n"); }
__device__ __forceinline__ void cp_wait_all() { asm volatile("cp.async.wait_group 0;\n"); }

// ---------------------------------------------------------------------------
// 1) dynamic-kernel MLP
// ---------------------------------------------------------------------------
__global__ void mlp_kernel(const float* __restrict__ d,
                           const float* __restrict__ k1a, const float* __restrict__ k2a,
                           const float* __restrict__ k1b, const float* __restrict__ k2b,
                           float* __restrict__ kern1, float* __restrict__ kern2)
{
    int b = blockIdx.x, stage = blockIdx.y;
    const float* k1 = stage ? k1b : k1a;
    const float* k2 = stage ? k2b : k2a;
    float* ko = stage ? kern2 : kern1;
    __shared__ float dd[64], hid[64];
    int t = threadIdx.x;
    dd[t] = d[b*64 + t];
    __syncthreads();
    float s = 0.f;
#pragma unroll 8
    for (int i = 0; i < 64; i++) s += dd[i] * k1[i*64 + t];
    hid[t] = leaky01(s);
    __syncthreads();
#pragma unroll
    for (int r = 0; r < 9; r++) {
        int o = r*64 + t;
        float s2 = 0.f;
#pragma unroll 8
        for (int i = 0; i < 64; i++) s2 += hid[i] * k2[i*576 + o];
        ko[b*576 + o] = s2;
    }
}

// ---------------------------------------------------------------------------
// 2) gating map from fp32 input (stage 1 only, reads x)
// ---------------------------------------------------------------------------
__global__ void gate_kernel(const float* __restrict__ in,
                            const float* __restrict__ cw,
                            const float* __restrict__ cb,
                            float* __restrict__ M)
{
    __shared__ float scw[C_];
    if (threadIdx.x < C_) scw[threadIdx.x] = cw[threadIdx.x];
    __syncthreads();
    int idx4 = blockIdx.x * blockDim.x + threadIdx.x;
    int b = idx4 / (HW_/4);
    int hw4 = idx4 - b * (HW_/4);
    const float* p = in + (size_t)b * CHW_ + hw4 * 4;
    float bias = cb[0];
    float4 s = make_float4(bias, bias, bias, bias);
#pragma unroll 8
    for (int c = 0; c < C_; c++) {
        float4 v = *(const float4*)(p + (size_t)c * HW_);
        float w = scw[c];
        s.x += w*v.x; s.y += w*v.y; s.z += w*v.z; s.w += w*v.w;
    }
    float4 r;
    r.x = 1.f/(1.f+expf(-s.x)); r.y = 1.f/(1.f+expf(-s.y));
    r.z = 1.f/(1.f+expf(-s.z)); r.w = 1.f/(1.f+expf(-s.w));
    *(float4*)&M[(size_t)b*HW_ + hw4*4] = r;
}

// ---------------------------------------------------------------------------
// 3) fused RDA, float4 — writes PACKED (bf16hi<<16|bf16lo)
// ---------------------------------------------------------------------------
__global__ void rda_kernel(const float* __restrict__ in,
                           const float* __restrict__ kern,
                           const float* __restrict__ M,
                           u32* __restrict__ outp)
{
    int idx4 = blockIdx.x * blockDim.x + threadIdx.x;
    int c = blockIdx.y, b = blockIdx.z;
    int h  = idx4 >> 5;
    int wq = (idx4 & 31) * 4;

    const float* k = kern + (b*C_ + c) * 9;
    float kk[9];
#pragma unroll
    for (int i = 0; i < 9; i++) kk[i] = k[i];

    const float* p = in + ((size_t)b*C_ + c) * HW_;
    float4 dw = make_float4(0.f, 0.f, 0.f, 0.f);
    float4 mid_c = *(const float4*)(p + h * W_ + wq);

#pragma unroll
    for (int r = 0; r < 3; r++) {
        int gy = h - 1 + r;
        if (gy < 0 || gy >= H_) continue;
        const float* rowp = p + gy * W_;
        float4 mid = (r == 1) ? mid_c : *(const float4*)(rowp + wq);
        float left  = (wq > 0)   ? rowp[wq - 1] : 0.f;
        float right = (wq < 124) ? rowp[wq + 4] : 0.f;
        float t0 = kk[r*3+0], t1 = kk[r*3+1], t2 = kk[r*3+2];
        dw.x += t0*left  + t1*mid.x + t2*mid.y;
        dw.y += t0*mid.x + t1*mid.y + t2*mid.z;
        dw.z += t0*mid.y + t1*mid.z + t2*mid.w;
        dw.w += t0*mid.z + t1*mid.w + t2*right;
    }

    float4 m = *(const float4*)&M[(size_t)b*HW_ + h*W_ + wq];
    uint4 o;
    o.x = pack_hilo(leaky01(leaky01(dw.x)*m.x + mid_c.x));
    o.y = pack_hilo(leaky01(leaky01(dw.y)*m.y + mid_c.y));
    o.z = pack_hilo(leaky01(leaky01(dw.z)*m.z + mid_c.z));
    o.w = pack_hilo(leaky01(leaky01(dw.w)*m.w + mid_c.w));
    *(uint4*)&outp[((size_t)b*C_ + c)*HW_ + h*W_ + wq] = o;
}

// ---------------------------------------------------------------------------
// 3b) weight prep: fp32 OIHW -> bf16 hi/lo in m16n8k16 A-fragment order.
// ---------------------------------------------------------------------------
__global__ void wprep_kernel(const float* __restrict__ w1,
                             const float* __restrict__ w2)
{
    int idx = blockIdx.x * blockDim.x + threadIdx.x;
    if (idx >= 2*4*9*4*2*32*4) return;
    int t = idx;
    int r    = t & 3;  t >>= 2;
    int lane = t & 31; t >>= 5;
    int q    = t & 1;  t >>= 1;
    int mt   = t & 3;  t >>= 2;
    int s9   = t % 9;  t /= 9;
    int chunk= t & 3;  t >>= 2;
    int s2   = t;

    int g = lane >> 2, tig = lane & 3;
    int co = mt*16 + g + (r & 1)*8;
    int k0 = s9*16 + 2*tig + (r >> 1)*8;
    int k1 = k0 + 1;

    const float* w = s2 ? w2 : w1;
    int ci0 = k0/9, tap0 = k0 - ci0*9;
    int ci1 = k1/9, tap1 = k1 - ci1*9;
    float w0 = w[(co*C_ + chunk*16 + ci0)*9 + tap0];
    float w1v= w[(co*C_ + chunk*16 + ci1)*9 + tap1];

    u16 p0, p1;
    if (q == 0) {
        __nv_bfloat16 h0 = __float2bfloat16(w0), h1 = __float2bfloat16(w1v);
        p0 = *reinterpret_cast<u16*>(&h0); p1 = *reinterpret_cast<u16*>(&h1);
    } else {
        __nv_bfloat16 h0 = __float2bfloat16(w0);
        __nv_bfloat16 l0 = __float2bfloat16(w0 - __bfloat162float(h0));
        __nv_bfloat16 h1 = __float2bfloat16(w1v);
        __nv_bfloat16 l1 = __float2bfloat16(w1v - __bfloat162float(h1));
        p0 = *reinterpret_cast<u16*>(&l0); p1 = *reinterpret_cast<u16*>(&l1);
    }
    g_wA[idx] = ((u32)p1 << 16) | (u32)p0;
}

// ---------------------------------------------------------------------------
// 4) mma.sync conv v5: block = 1 row, 128 threads = 4 warps.
//    Warp wid covers px [wid*32, wid*32+32) (nt=4), all 64 co (mt=4).
//    launch_bounds(128,2): 256-reg budget, 2 CTA/SM (8 warps/SM).
//    Input: cp.async double-buffered. Weights: LDG.128 (L1-resident).
// ---------------------------------------------------------------------------
#define RW2  136
#define WCH  9216                        // u32 per fragment-weight chunk
#define ICH3 (16*3*RW2)                  // 6528 u32 per input chunk
#define SMEM_DYN (2*ICH3*4)              // 52224 B

__global__ void __launch_bounds__(128, 2)
conv_mma(const u32* __restrict__ pin,
         const u32* __restrict__ wA,
         const float* __restrict__ bias,
         const float* __restrict__ residual,
         float* __restrict__ out,
         int apply_leaky,
         const float* __restrict__ gcw,   // fused gate weights (or null)
         const float* __restrict__ gcb,
         float* __restrict__ Mout)
{
    extern __shared__ u32 dsm[];
    u32* iS[2] = { dsm, dsm + ICH3 };

    int tid = threadIdx.x;
    int wid = tid >> 5;
    int lane = tid & 31;
    int g = lane >> 2, tig = lane & 3;
    int warpbase = wid * 32;
    int h = blockIdx.x, b = blockIdx.z;

    // zero input buffers once (halo cols + off-image rows stay 0)
    for (int i = tid; i < 2*ICH3; i += 128) dsm[i] = 0;

    u32 iS_a[2] = { smem_u32(iS[0]), smem_u32(iS[1]) };
    __syncthreads();

    // prefetch input chunk: 16 ci x 3 rows x 32 segs = 1536 x 16B
    auto prefetch = [&](int chunk, int buf) {
#pragma unroll
        for (int i = 0; i < 12; i++) {
            int idx = tid + i*128;               // 0..1535
            int ci  = idx / 96;
            int rem = idx - ci*96;
            int rr  = rem >> 5;                  // 0..2
            int seg = rem & 31;
            int gy  = h - 1 + rr;
            if (gy >= 0 && gy < H_) {
                u32 dst = iS_a[buf] + (u32)(((ci*3 + rr)*RW2 + 4 + seg*4) * 4);
                cp_async16(dst, pin + (((size_t)b*C_ + chunk*16 + ci)*H_ + gy)*W_ + seg*4);
            }
        }
    };

    float D[4][4][4];
#pragma unroll
    for (int mt = 0; mt < 4; mt++)
#pragma unroll
        for (int nt = 0; nt < 4; nt++)
#pragma unroll
            for (int i = 0; i < 4; i++) D[mt][nt][i] = 0.f;

    prefetch(0, 0);
    cp_commit();

    for (int chunk = 0; chunk < 4; chunk++) {
        cp_wait_all();
        __syncthreads();

        if (chunk < 3) {
            prefetch(chunk + 1, (chunk + 1) & 1);
            cp_commit();
        }

        const u32* inS = iS[chunk & 1];
        const u32* wc  = wA + chunk * WCH;

#pragma unroll
        for (int s = 0; s < 9; s++) {
            uint4 Ah[4], Al[4];
#pragma unroll
            for (int mt = 0; mt < 4; mt++) {
                const uint4* base = (const uint4*)(wc + ((s*4 + mt)*2)*128 + lane*4);
                Ah[mt] = __ldg(base);
                Al[mt] = __ldg(base + 32);       // +128 u32 = +32 uint4
            }
#pragma unroll
            for (int nt = 0; nt < 4; nt++) {
                int n = warpbase + nt*8 + g;
                u32 bh[2], bl[2];
#pragma unroll
                for (int r = 0; r < 2; r++) {
                    int k0 = s*16 + 2*tig + r*8;
                    int k1 = k0 + 1;
                    int ci0 = k0/9, tap0 = k0 - ci0*9;
                    int ci1 = k1/9, tap1 = k1 - ci1*9;
                    u32 v0 = inS[(ci0*3 + tap0/3)*RW2 + n + (tap0 % 3) + 3];
                    u32 v1 = inS[(ci1*3 + tap1/3)*RW2 + n + (tap1 % 3) + 3];
                    bh[r] = __byte_perm(v0, v1, 0x7632);
                    bl[r] = __byte_perm(v0, v1, 0x5410);
                }
#pragma unroll
                for (int mt = 0; mt < 4; mt++) {
                    mma16816(D[mt][nt], (const u32*)&Ah[mt], bh[0], bh[1]);
                    mma16816(D[mt][nt], (const u32*)&Ah[mt], bl[0], bl[1]);
                    mma16816(D[mt][nt], (const u32*)&Al[mt], bh[0], bh[1]);
                }
            }
        }
    }

    // ---- epilogue (+ optional fused gate) ----
    float bv[4][2], cwv[4][2];
#pragma unroll
    for (int mt = 0; mt < 4; mt++) {
        int co0 = mt*16 + g;
        bv[mt][0] = bias[co0];
        bv[mt][1] = bias[co0 + 8];
        if (gcw) { cwv[mt][0] = gcw[co0]; cwv[mt][1] = gcw[co0 + 8]; }
    }
    float gb = gcw ? gcb[0] : 0.f;

#pragma unroll
    for (int nt = 0; nt < 4; nt++) {
        int px = warpbase + nt*8 + 2*tig;
        float gx = 0.f, gy = 0.f;
#pragma unroll
        for (int mt = 0; mt < 4; mt++) {
            int co0 = mt*16 + g;
            size_t o0 = (((size_t)b*C_ + co0    )*H_ + h)*W_ + px;
            size_t o1 = (((size_t)b*C_ + co0 + 8)*H_ + h)*W_ + px;
            float2 v0 = make_float2(D[mt][nt][0] + bv[mt][0], D[mt][nt][1] + bv[mt][0]);
            float2 v1 = make_float2(D[mt][nt][2] + bv[mt][1], D[mt][nt][3] + bv[mt][1]);
            if (apply_leaky) {
                v0.x = leaky01(v0.x); v0.y = leaky01(v0.y);
                v1.x = leaky01(v1.x); v1.y = leaky01(v1.y);
            }
            if (residual) {
                const float2 r0 = *(const float2*)&residual[o0];
                const float2 r1 = *(const float2*)&residual[o1];
                v0.x += r0.x; v0.y += r0.y; v1.x += r1.x; v1.y += r1.y;
            }
            *(float2*)&out[o0] = v0;
            *(float2*)&out[o1] = v1;
            if (gcw) {
                gx += v0.x*cwv[mt][0] + v1.x*cwv[mt][1];
                gy += v0.y*cwv[mt][0] + v1.y*cwv[mt][1];
            }
        }
        if (gcw) {
            // reduce over g-lanes (co groups): lanes differ in bits 2..4
#pragma unroll
            for (int ofs = 4; ofs <= 16; ofs <<= 1) {
                gx += __shfl_xor_sync(0xFFFFFFFFu, gx, ofs);
                gy += __shfl_xor_sync(0xFFFFFFFFu, gy, ofs);
            }
            if (g == 0) {
                float2 mo;
                mo.x = 1.f / (1.f + expf(-(gx + gb)));
                mo.y = 1.f / (1.f + expf(-(gy + gb)));
                *(float2*)&Mout[(size_t)b*HW_ + h*W_ + px] = mo;
            }
        }
    }
}

// ---------------------------------------------------------------------------
// launch
// ---------------------------------------------------------------------------
extern "C" void kernel_launch(void* const* d_in, const int* in_sizes, int n_in,
                              void* d_out, int out_size)
{
    const float* x       = (const float*)d_in[0];
    const float* d       = (const float*)d_in[1];
    const float* da1_k1  = (const float*)d_in[2];
    const float* da1_k2  = (const float*)d_in[3];
    const float* da1_cw  = (const float*)d_in[4];
    const float* da1_cb  = (const float*)d_in[5];
    const float* da2_k1  = (const float*)d_in[6];
    const float* da2_k2  = (const float*)d_in[7];
    const float* da2_cw  = (const float*)d_in[8];
    const float* da2_cb  = (const float*)d_in[9];
    const float* conv1_w = (const float*)d_in[10];
    const float* conv1_b = (const float*)d_in[11];
    const float* conv2_w = (const float*)d_in[12];
    const float* conv2_b = (const float*)d_in[13];
    float* out = (float*)d_out;

    u32 *buf1, *wa; float *buf2, *gate, *kern1, *kern2;
    cudaGetSymbolAddress((void**)&buf1,  g_buf1);
    cudaGetSymbolAddress((void**)&buf2,  g_buf2);
    cudaGetSymbolAddress((void**)&gate,  g_gate);
    cudaGetSymbolAddress((void**)&kern1, g_kern1);
    cudaGetSymbolAddress((void**)&kern2, g_kern2);
    cudaGetSymbolAddress((void**)&wa,    g_wA);

    cudaFuncSetAttribute(conv_mma, cudaFuncAttributeMaxDynamicSharedMemorySize, SMEM_DYN);

    mlp_kernel<<<dim3(B_, 2), 64>>>(d, da1_k1, da1_k2, da2_k1, da2_k2, kern1, kern2);
    wprep_kernel<<<(2*4*9*4*2*32*4 + 255)/256, 256>>>(conv1_w, conv2_w);

    gate_kernel<<<(B_*HW_/4)/256, 256>>>(x, da1_cw, da1_cb, gate);
    rda_kernel<<<dim3(HW_/4/256, C_, B_), 256>>>(x, kern1, gate, buf1);

    // conv1 + leaky, with fused gate2 (writes M for rda2 into `gate`)
    conv_mma<<<dim3(H_, 1, B_), 128, SMEM_DYN>>>(buf1, wa, conv1_b, nullptr,
                                                 buf2, 1, da2_cw, da2_cb, gate);

    rda_kernel<<<dim3(HW_/4/256, C_, B_), 256>>>(buf2, kern2, gate, buf1);

    // conv2 + residual(x)
    conv_mma<<<dim3(H_, 1, B_), 128, SMEM_DYN>>>(buf1, wa + 4*WCH, conv2_b, x,
                                                 out, 0, nullptr, nullptr, nullptr);
}

// round 16
// speedup vs baseline: 1.2893x; 1.0251x over previous
#include <cuda_runtime.h>
#include <cuda_bf16.h>
#include <math.h>

// ---------------------------------------------------------------------------
// RDAB block: x[16,64,128,128] fp32
// Round 16: barrier-free conv mainloop — entire 64-ci input slab resident in
// smem (102 KB, one cp.async burst, one sync), weights LDG.128 software-
// pipelined one K-step ahead. Gate2 stays fused in conv1 epilogue.
// ---------------------------------------------------------------------------

#define B_   16
#define C_   64
#define H_   128
#define W_   128
#define HW_  (H_*W_)
#define CHW_ (C_*HW_)

typedef unsigned long long u64;
typedef unsigned int u32;
typedef unsigned short u16;

__device__ u32   g_buf1[(size_t)B_*CHW_];   // packed (bf16hi<<16)|bf16lo
__device__ float g_buf2[(size_t)B_*CHW_];
__device__ float g_gate[(size_t)B_*HW_];
__device__ float g_kern1[B_*C_*9];
__device__ float g_kern2[B_*C_*9];
// fragment-ordered weights: [conv2][chunk4][step9][mt4][half2][lane32][reg4] u32
__device__ u32   g_wA[2*4*9*4*2*32*4];

__device__ __forceinline__ float leaky01(float v) { return v > 0.f ? v : 0.1f*v; }

__device__ __forceinline__ u32 pack_hilo(float v) {
    __nv_bfloat16 h = __float2bfloat16(v);
    float vh = __bfloat162float(h);
    __nv_bfloat16 l = __float2bfloat16(v - vh);
    u16 hb = *reinterpret_cast<u16*>(&h);
    u16 lb = *reinterpret_cast<u16*>(&l);
    return ((u32)hb << 16) | (u32)lb;
}
__device__ __forceinline__ void mma16816(float* c, const u32* a, u32 b0, u32 b1) {
    asm volatile(
        "mma.sync.aligned.m16n8k16.row.col.f32.bf16.bf16.f32 "
        "{%0,%1,%2,%3}, {%4,%5,%6,%7}, {%8,%9}, {%0,%1,%2,%3};"
        : "+f"(c[0]), "+f"(c[1]), "+f"(c[2]), "+f"(c[3])
        : "r"(a[0]), "r"(a[1]), "r"(a[2]), "r"(a[3]), "r"(b0), "r"(b1));
}
__device__ __forceinline__ u32 smem_u32(const void* p) {
    u32 a;
    asm("{ .reg .u64 t; cvta.to.shared.u64 t, %1; cvt.u32.u64 %0, t; }"
        : "=r"(a) : "l"(p));
    return a;
}
__device__ __forceinline__ void cp_async16(u32 dst, const void* src) {
    asm volatile("cp.async.ca.shared.global [%0], [%1], 16;\n" :: "r"(dst), "l"(src));
}
__device__ __forceinline__ void cp_commit() { asm volatile("cp.async.commit_group;\n"); }
__device__ __forceinline__ void cp_wait_all() { asm volatile("cp.async.wait_group 0;\n"); }

// ---------------------------------------------------------------------------
// 1) dynamic-kernel MLP
// ---------------------------------------------------------------------------
__global__ void mlp_kernel(const float* __restrict__ d,
                           const float* __restrict__ k1a, const float* __restrict__ k2a,
                           const float* __restrict__ k1b, const float* __restrict__ k2b,
                           float* __restrict__ kern1, float* __restrict__ kern2)
{
    int b = blockIdx.x, stage = blockIdx.y;
    const float* k1 = stage ? k1b : k1a;
    const float* k2 = stage ? k2b : k2a;
    float* ko = stage ? kern2 : kern1;
    __shared__ float dd[64], hid[64];
    int t = threadIdx.x;
    dd[t] = d[b*64 + t];
    __syncthreads();
    float s = 0.f;
#pragma unroll 8
    for (int i = 0; i < 64; i++) s += dd[i] * k1[i*64 + t];
    hid[t] = leaky01(s);
    __syncthreads();
#pragma unroll
    for (int r = 0; r < 9; r++) {
        int o = r*64 + t;
        float s2 = 0.f;
#pragma unroll 8
        for (int i = 0; i < 64; i++) s2 += hid[i] * k2[i*576 + o];
        ko[b*576 + o] = s2;
    }
}

// ---------------------------------------------------------------------------
// 2) gating map from fp32 input (stage 1 only, reads x)
// ---------------------------------------------------------------------------
__global__ void gate_kernel(const float* __restrict__ in,
                            const float* __restrict__ cw,
                            const float* __restrict__ cb,
                            float* __restrict__ M)
{
    __shared__ float scw[C_];
    if (threadIdx.x < C_) scw[threadIdx.x] = cw[threadIdx.x];
    __syncthreads();
    int idx4 = blockIdx.x * blockDim.x + threadIdx.x;
    int b = idx4 / (HW_/4);
    int hw4 = idx4 - b * (HW_/4);
    const float* p = in + (size_t)b * CHW_ + hw4 * 4;
    float bias = cb[0];
    float4 s = make_float4(bias, bias, bias, bias);
#pragma unroll 8
    for (int c = 0; c < C_; c++) {
        float4 v = *(const float4*)(p + (size_t)c * HW_);
        float w = scw[c];
        s.x += w*v.x; s.y += w*v.y; s.z += w*v.z; s.w += w*v.w;
    }
    float4 r;
    r.x = 1.f/(1.f+expf(-s.x)); r.y = 1.f/(1.f+expf(-s.y));
    r.z = 1.f/(1.f+expf(-s.z)); r.w = 1.f/(1.f+expf(-s.w));
    *(float4*)&M[(size_t)b*HW_ + hw4*4] = r;
}

// ---------------------------------------------------------------------------
// 3) fused RDA, float4 — writes PACKED (bf16hi<<16|bf16lo)
// ---------------------------------------------------------------------------
__global__ void rda_kernel(const float* __restrict__ in,
                           const float* __restrict__ kern,
                           const float* __restrict__ M,
                           u32* __restrict__ outp)
{
    int idx4 = blockIdx.x * blockDim.x + threadIdx.x;
    int c = blockIdx.y, b = blockIdx.z;
    int h  = idx4 >> 5;
    int wq = (idx4 & 31) * 4;

    const float* k = kern + (b*C_ + c) * 9;
    float kk[9];
#pragma unroll
    for (int i = 0; i < 9; i++) kk[i] = k[i];

    const float* p = in + ((size_t)b*C_ + c) * HW_;
    float4 dw = make_float4(0.f, 0.f, 0.f, 0.f);
    float4 mid_c = *(const float4*)(p + h * W_ + wq);

#pragma unroll
    for (int r = 0; r < 3; r++) {
        int gy = h - 1 + r;
        if (gy < 0 || gy >= H_) continue;
        const float* rowp = p + gy * W_;
        float4 mid = (r == 1) ? mid_c : *(const float4*)(rowp + wq);
        float left  = (wq > 0)   ? rowp[wq - 1] : 0.f;
        float right = (wq < 124) ? rowp[wq + 4] : 0.f;
        float t0 = kk[r*3+0], t1 = kk[r*3+1], t2 = kk[r*3+2];
        dw.x += t0*left  + t1*mid.x + t2*mid.y;
        dw.y += t0*mid.x + t1*mid.y + t2*mid.z;
        dw.z += t0*mid.y + t1*mid.z + t2*mid.w;
        dw.w += t0*mid.z + t1*mid.w + t2*right;
    }

    float4 m = *(const float4*)&M[(size_t)b*HW_ + h*W_ + wq];
    uint4 o;
    o.x = pack_hilo(leaky01(leaky01(dw.x)*m.x + mid_c.x));
    o.y = pack_hilo(leaky01(leaky01(dw.y)*m.y + mid_c.y));
    o.z = pack_hilo(leaky01(leaky01(dw.z)*m.z + mid_c.z));
    o.w = pack_hilo(leaky01(leaky01(dw.w)*m.w + mid_c.w));
    *(uint4*)&outp[((size_t)b*C_ + c)*HW_ + h*W_ + wq] = o;
}

// ---------------------------------------------------------------------------
// 3b) weight prep: fp32 OIHW -> bf16 hi/lo in m16n8k16 A-fragment order.
// ---------------------------------------------------------------------------
__global__ void wprep_kernel(const float* __restrict__ w1,
                             const float* __restrict__ w2)
{
    int idx = blockIdx.x * blockDim.x + threadIdx.x;
    if (idx >= 2*4*9*4*2*32*4) return;
    int t = idx;
    int r    = t & 3;  t >>= 2;
    int lane = t & 31; t >>= 5;
    int q    = t & 1;  t >>= 1;
    int mt   = t & 3;  t >>= 2;
    int s9   = t % 9;  t /= 9;
    int chunk= t & 3;  t >>= 2;
    int s2   = t;

    int g = lane >> 2, tig = lane & 3;
    int co = mt*16 + g + (r & 1)*8;
    int k0 = s9*16 + 2*tig + (r >> 1)*8;
    int k1 = k0 + 1;

    const float* w = s2 ? w2 : w1;
    int ci0 = k0/9, tap0 = k0 - ci0*9;
    int ci1 = k1/9, tap1 = k1 - ci1*9;
    float w0 = w[(co*C_ + chunk*16 + ci0)*9 + tap0];
    float w1v= w[(co*C_ + chunk*16 + ci1)*9 + tap1];

    u16 p0, p1;
    if (q == 0) {
        __nv_bfloat16 h0 = __float2bfloat16(w0), h1 = __float2bfloat16(w1v);
        p0 = *reinterpret_cast<u16*>(&h0); p1 = *reinterpret_cast<u16*>(&h1);
    } else {
        __nv_bfloat16 h0 = __float2bfloat16(w0);
        __nv_bfloat16 l0 = __float2bfloat16(w0 - __bfloat162float(h0));
        __nv_bfloat16 h1 = __float2bfloat16(w1v);
        __nv_bfloat16 l1 = __float2bfloat16(w1v - __bfloat162float(h1));
        p0 = *reinterpret_cast<u16*>(&l0); p1 = *reinterpret_cast<u16*>(&l1);
    }
    g_wA[idx] = ((u32)p1 << 16) | (u32)p0;
}

// ---------------------------------------------------------------------------
// 4) mma.sync conv v6: block = 1 row, 128 threads = 4 warps.
//    ALL 64 ci input rows resident in smem (102 KB, one cp.async burst, one
//    sync) -> barrier-free 36-step mainloop. Weights LDG.128, software-
//    pipelined one step ahead (ping-pong fragment regs).
// ---------------------------------------------------------------------------
#define RW2  136
#define ICH_ALL (64*3*RW2)               // 26112 u32 = 104448 B
#define SMEM_DYN (ICH_ALL*4)

#define LOADFRAG(sg, AHs, ALs) do { \
    const u32* wb_ = wA + (u32)(sg)*1024 + lane*4; \
    AHs[0] = __ldg((const uint4*)(wb_        )); \
    ALs[0] = __ldg((const uint4*)(wb_ +  128)); \
    AHs[1] = __ldg((const uint4*)(wb_ +  256)); \
    ALs[1] = __ldg((const uint4*)(wb_ +  384)); \
    AHs[2] = __ldg((const uint4*)(wb_ +  512)); \
    ALs[2] = __ldg((const uint4*)(wb_ +  640)); \
    AHs[3] = __ldg((const uint4*)(wb_ +  768)); \
    ALs[3] = __ldg((const uint4*)(wb_ +  896)); \
} while (0)

__global__ void __launch_bounds__(128, 2)
conv_mma(const u32* __restrict__ pin,
         const u32* __restrict__ wA,
         const float* __restrict__ bias,
         const float* __restrict__ residual,
         float* __restrict__ out,
         int apply_leaky,
         const float* __restrict__ gcw,   // fused gate weights (or null)
         const float* __restrict__ gcb,
         float* __restrict__ gcbias_Mout, // Mout (reuse slot)
         float* __restrict__ Mout)
{
    extern __shared__ u32 inS[];

    int tid = threadIdx.x;
    int wid = tid >> 5;
    int lane = tid & 31;
    int g = lane >> 2, tig = lane & 3;
    int warpbase = wid * 32;
    int h = blockIdx.x, b = blockIdx.z;

    // zero slab once (halo cols + off-image rows stay 0)
    for (int i = tid; i < ICH_ALL; i += 128) inS[i] = 0;
    u32 iS_a = smem_u32(inS);
    __syncthreads();

    // stage ALL input: 64 ci x 3 rows x 32 segs = 6144 x 16B (one burst)
#pragma unroll
    for (int i = 0; i < 48; i++) {
        int idx = tid + i*128;               // 0..6143
        int ci  = idx / 96;
        int rem = idx - ci*96;
        int rr  = rem >> 5;                  // 0..2
        int seg = rem & 31;
        int gy  = h - 1 + rr;
        if (gy >= 0 && gy < H_) {
            u32 dst = iS_a + (u32)(((ci*3 + rr)*RW2 + 4 + seg*4) * 4);
            cp_async16(dst, pin + (((size_t)b*C_ + ci)*H_ + gy)*W_ + seg*4);
        }
    }
    cp_commit();

    float D[4][4][4];
#pragma unroll
    for (int mt = 0; mt < 4; mt++)
#pragma unroll
        for (int nt = 0; nt < 4; nt++)
#pragma unroll
            for (int i = 0; i < 4; i++) D[mt][nt][i] = 0.f;

    cp_wait_all();
    __syncthreads();                         // slab ready; no more barriers

    uint4 AH[2][4], AL[2][4];

    for (int c9 = 0; c9 < 4; c9++) {
        LOADFRAG(c9*9, AH[0], AL[0]);        // slot 0 for s=0
#pragma unroll
        for (int s = 0; s < 9; s++) {
            const int p = s & 1;
            if (s < 8) { LOADFRAG(c9*9 + s + 1, AH[p^1], AL[p^1]); }
#pragma unroll
            for (int nt = 0; nt < 4; nt++) {
                int n = warpbase + nt*8 + g;
                u32 bh[2], bl[2];
#pragma unroll
                for (int r = 0; r < 2; r++) {
                    int kl0 = s*16 + 2*tig + r*8;      // chunk-local k
                    int kl1 = kl0 + 1;
                    int ci0 = c9*16 + kl0/9, tap0 = kl0 % 9;
                    int ci1 = c9*16 + kl1/9, tap1 = kl1 % 9;
                    u32 v0 = inS[(ci0*3 + tap0/3)*RW2 + n + (tap0 % 3) + 3];
                    u32 v1 = inS[(ci1*3 + tap1/3)*RW2 + n + (tap1 % 3) + 3];
                    bh[r] = __byte_perm(v0, v1, 0x7632);
                    bl[r] = __byte_perm(v0, v1, 0x5410);
                }
#pragma unroll
                for (int mt = 0; mt < 4; mt++) {
                    mma16816(D[mt][nt], (const u32*)&AH[p][mt], bh[0], bh[1]);
                    mma16816(D[mt][nt], (const u32*)&AH[p][mt], bl[0], bl[1]);
                    mma16816(D[mt][nt], (const u32*)&AL[p][mt], bh[0], bh[1]);
                }
            }
        }
    }

    // ---- epilogue (+ optional fused gate) ----
    float bv[4][2], cwv[4][2];
#pragma unroll
    for (int mt = 0; mt < 4; mt++) {
        int co0 = mt*16 + g;
        bv[mt][0] = bias[co0];
        bv[mt][1] = bias[co0 + 8];
        if (gcw) { cwv[mt][0] = gcw[co0]; cwv[mt][1] = gcw[co0 + 8]; }
    }
    float gb = gcw ? gcb[0] : 0.f;

#pragma unroll
    for (int nt = 0; nt < 4; nt++) {
        int px = warpbase + nt*8 + 2*tig;
        float gx = 0.f, gy = 0.f;
#pragma unroll
        for (int mt = 0; mt < 4; mt++) {
            int co0 = mt*16 + g;
            size_t o0 = (((size_t)b*C_ + co0    )*H_ + h)*W_ + px;
            size_t o1 = (((size_t)b*C_ + co0 + 8)*H_ + h)*W_ + px;
            float2 v0 = make_float2(D[mt][nt][0] + bv[mt][0], D[mt][nt][1] + bv[mt][0]);
            float2 v1 = make_float2(D[mt][nt][2] + bv[mt][1], D[mt][nt][3] + bv[mt][1]);
            if (apply_leaky) {
                v0.x = leaky01(v0.x); v0.y = leaky01(v0.y);
                v1.x = leaky01(v1.x); v1.y = leaky01(v1.y);
            }
            if (residual) {
                const float2 r0 = *(const float2*)&residual[o0];
                const float2 r1 = *(const float2*)&residual[o1];
                v0.x += r0.x; v0.y += r0.y; v1.x += r1.x; v1.y += r1.y;
            }
            *(float2*)&out[o0] = v0;
            *(float2*)&out[o1] = v1;
            if (gcw) {
                gx += v0.x*cwv[mt][0] + v1.x*cwv[mt][1];
                gy += v0.y*cwv[mt][0] + v1.y*cwv[mt][1];
            }
        }
        if (gcw) {
#pragma unroll
            for (int ofs = 4; ofs <= 16; ofs <<= 1) {
                gx += __shfl_xor_sync(0xFFFFFFFFu, gx, ofs);
                gy += __shfl_xor_sync(0xFFFFFFFFu, gy, ofs);
            }
            if (g == 0) {
                float2 mo;
                mo.x = 1.f / (1.f + expf(-(gx + gb)));
                mo.y = 1.f / (1.f + expf(-(gy + gb)));
                *(float2*)&Mout[(size_t)b*HW_ + h*W_ + px] = mo;
            }
        }
    }
}

// ---------------------------------------------------------------------------
// launch
// ---------------------------------------------------------------------------
extern "C" void kernel_launch(void* const* d_in, const int* in_sizes, int n_in,
                              void* d_out, int out_size)
{
    const float* x       = (const float*)d_in[0];
    const float* d       = (const float*)d_in[1];
    const float* da1_k1  = (const float*)d_in[2];
    const float* da1_k2  = (const float*)d_in[3];
    const float* da1_cw  = (const float*)d_in[4];
    const float* da1_cb  = (const float*)d_in[5];
    const float* da2_k1  = (const float*)d_in[6];
    const float* da2_k2  = (const float*)d_in[7];
    const float* da2_cw  = (const float*)d_in[8];
    const float* da2_cb  = (const float*)d_in[9];
    const float* conv1_w = (const float*)d_in[10];
    const float* conv1_b = (const float*)d_in[11];
    const float* conv2_w = (const float*)d_in[12];
    const float* conv2_b = (const float*)d_in[13];
    float* out = (float*)d_out;

    u32 *buf1, *wa; float *buf2, *gate, *kern1, *kern2;
    cudaGetSymbolAddress((void**)&buf1,  g_buf1);
    cudaGetSymbolAddress((void**)&buf2,  g_buf2);
    cudaGetSymbolAddress((void**)&gate,  g_gate);
    cudaGetSymbolAddress((void**)&kern1, g_kern1);
    cudaGetSymbolAddress((void**)&kern2, g_kern2);
    cudaGetSymbolAddress((void**)&wa,    g_wA);

    cudaFuncSetAttribute(conv_mma, cudaFuncAttributeMaxDynamicSharedMemorySize, SMEM_DYN);

    mlp_kernel<<<dim3(B_, 2), 64>>>(d, da1_k1, da1_k2, da2_k1, da2_k2, kern1, kern2);
    wprep_kernel<<<(2*4*9*4*2*32*4 + 255)/256, 256>>>(conv1_w, conv2_w);

    gate_kernel<<<(B_*HW_/4)/256, 256>>>(x, da1_cw, da1_cb, gate);
    rda_kernel<<<dim3(HW_/4/256, C_, B_), 256>>>(x, kern1, gate, buf1);

    // conv1 + leaky, with fused gate2 (writes M for rda2 into `gate`)
    conv_mma<<<dim3(H_, 1, B_), 128, SMEM_DYN>>>(buf1, wa, conv1_b, nullptr,
                                                 buf2, 1, da2_cw, da2_cb,
                                                 nullptr, gate);

    rda_kernel<<<dim3(HW_/4/256, C_, B_), 256>>>(buf2, kern2, gate, buf1);

    // conv2 + residual(x)
    conv_mma<<<dim3(H_, 1, B_), 128, SMEM_DYN>>>(buf1, wa + 4*9216, conv2_b, x,
                                                 out, 0, nullptr, nullptr,
                                                 nullptr, nullptr);
}

// round 17
// speedup vs baseline: 1.2981x; 1.0068x over previous
#include <cuda_runtime.h>
#include <cuda_bf16.h>
#include <math.h>

// ---------------------------------------------------------------------------
// RDAB block: x[16,64,128,128] fp32
// Round 17: conv mainloop reordered term-major — B-fragments hoisted per
// K-step, the 3 split-term MMAs of each accumulator separated by 16
// independent MMAs (kills RAW chains on the HMMA pipe). Slab-resident input
// (R16), weights LDG.128 pipelined, gate2 fused in conv1.
// ---------------------------------------------------------------------------

#define B_   16
#define C_   64
#define H_   128
#define W_   128
#define HW_  (H_*W_)
#define CHW_ (C_*HW_)

typedef unsigned long long u64;
typedef unsigned int u32;
typedef unsigned short u16;

__device__ u32   g_buf1[(size_t)B_*CHW_];   // packed (bf16hi<<16)|bf16lo
__device__ float g_buf2[(size_t)B_*CHW_];
__device__ float g_gate[(size_t)B_*HW_];
__device__ float g_kern1[B_*C_*9];
__device__ float g_kern2[B_*C_*9];
// fragment-ordered weights: [conv2][chunk4][step9][mt4][half2][lane32][reg4] u32
__device__ u32   g_wA[2*4*9*4*2*32*4];

__device__ __forceinline__ float leaky01(float v) { return v > 0.f ? v : 0.1f*v; }

__device__ __forceinline__ u32 pack_hilo(float v) {
    __nv_bfloat16 h = __float2bfloat16(v);
    float vh = __bfloat162float(h);
    __nv_bfloat16 l = __float2bfloat16(v - vh);
    u16 hb = *reinterpret_cast<u16*>(&h);
    u16 lb = *reinterpret_cast<u16*>(&l);
    return ((u32)hb << 16) | (u32)lb;
}
__device__ __forceinline__ void mma16816(float* c, const u32* a, u32 b0, u32 b1) {
    asm volatile(
        "mma.sync.aligned.m16n8k16.row.col.f32.bf16.bf16.f32 "
        "{%0,%1,%2,%3}, {%4,%5,%6,%7}, {%8,%9}, {%0,%1,%2,%3};"
        : "+f"(c[0]), "+f"(c[1]), "+f"(c[2]), "+f"(c[3])
        : "r"(a[0]), "r"(a[1]), "r"(a[2]), "r"(a[3]), "r"(b0), "r"(b1));
}
__device__ __forceinline__ u32 smem_u32(const void* p) {
    u32 a;
    asm("{ .reg .u64 t; cvta.to.shared.u64 t, %1; cvt.u32.u64 %0, t; }"
        : "=r"(a) : "l"(p));
    return a;
}
__device__ __forceinline__ void cp_async16(u32 dst, const void* src) {
    asm volatile("cp.async.ca.shared.global [%0], [%1], 16;\n" :: "r"(dst), "l"(src));
}
__device__ __forceinline__ void cp_commit() { asm volatile("cp.async.commit_group;\n"); }
__device__ __forceinline__ void cp_wait_all() { asm volatile("cp.async.wait_group 0;\n"); }

// ---------------------------------------------------------------------------
// 1) dynamic-kernel MLP
// ---------------------------------------------------------------------------
__global__ void mlp_kernel(const float* __restrict__ d,
                           const float* __restrict__ k1a, const float* __restrict__ k2a,
                           const float* __restrict__ k1b, const float* __restrict__ k2b,
                           float* __restrict__ kern1, float* __restrict__ kern2)
{
    int b = blockIdx.x, stage = blockIdx.y;
    const float* k1 = stage ? k1b : k1a;
    const float* k2 = stage ? k2b : k2a;
    float* ko = stage ? kern2 : kern1;
    __shared__ float dd[64], hid[64];
    int t = threadIdx.x;
    dd[t] = d[b*64 + t];
    __syncthreads();
    float s = 0.f;
#pragma unroll 8
    for (int i = 0; i < 64; i++) s += dd[i] * k1[i*64 + t];
    hid[t] = leaky01(s);
    __syncthreads();
#pragma unroll
    for (int r = 0; r < 9; r++) {
        int o = r*64 + t;
        float s2 = 0.f;
#pragma unroll 8
        for (int i = 0; i < 64; i++) s2 += hid[i] * k2[i*576 + o];
        ko[b*576 + o] = s2;
    }
}

// ---------------------------------------------------------------------------
// 2) gating map from fp32 input (stage 1 only, reads x)
// ---------------------------------------------------------------------------
__global__ void gate_kernel(const float* __restrict__ in,
                            const float* __restrict__ cw,
                            const float* __restrict__ cb,
                            float* __restrict__ M)
{
    __shared__ float scw[C_];
    if (threadIdx.x < C_) scw[threadIdx.x] = cw[threadIdx.x];
    __syncthreads();
    int idx4 = blockIdx.x * blockDim.x + threadIdx.x;
    int b = idx4 / (HW_/4);
    int hw4 = idx4 - b * (HW_/4);
    const float* p = in + (size_t)b * CHW_ + hw4 * 4;
    float bias = cb[0];
    float4 s = make_float4(bias, bias, bias, bias);
#pragma unroll 8
    for (int c = 0; c < C_; c++) {
        float4 v = *(const float4*)(p + (size_t)c * HW_);
        float w = scw[c];
        s.x += w*v.x; s.y += w*v.y; s.z += w*v.z; s.w += w*v.w;
    }
    float4 r;
    r.x = 1.f/(1.f+expf(-s.x)); r.y = 1.f/(1.f+expf(-s.y));
    r.z = 1.f/(1.f+expf(-s.z)); r.w = 1.f/(1.f+expf(-s.w));
    *(float4*)&M[(size_t)b*HW_ + hw4*4] = r;
}

// ---------------------------------------------------------------------------
// 3) fused RDA, float4 — writes PACKED (bf16hi<<16|bf16lo)
// ---------------------------------------------------------------------------
__global__ void rda_kernel(const float* __restrict__ in,
                           const float* __restrict__ kern,
                           const float* __restrict__ M,
                           u32* __restrict__ outp)
{
    int idx4 = blockIdx.x * blockDim.x + threadIdx.x;
    int c = blockIdx.y, b = blockIdx.z;
    int h  = idx4 >> 5;
    int wq = (idx4 & 31) * 4;

    const float* k = kern + (b*C_ + c) * 9;
    float kk[9];
#pragma unroll
    for (int i = 0; i < 9; i++) kk[i] = k[i];

    const float* p = in + ((size_t)b*C_ + c) * HW_;
    float4 dw = make_float4(0.f, 0.f, 0.f, 0.f);
    float4 mid_c = *(const float4*)(p + h * W_ + wq);

#pragma unroll
    for (int r = 0; r < 3; r++) {
        int gy = h - 1 + r;
        if (gy < 0 || gy >= H_) continue;
        const float* rowp = p + gy * W_;
        float4 mid = (r == 1) ? mid_c : *(const float4*)(rowp + wq);
        float left  = (wq > 0)   ? rowp[wq - 1] : 0.f;
        float right = (wq < 124) ? rowp[wq + 4] : 0.f;
        float t0 = kk[r*3+0], t1 = kk[r*3+1], t2 = kk[r*3+2];
        dw.x += t0*left  + t1*mid.x + t2*mid.y;
        dw.y += t0*mid.x + t1*mid.y + t2*mid.z;
        dw.z += t0*mid.y + t1*mid.z + t2*mid.w;
        dw.w += t0*mid.z + t1*mid.w + t2*right;
    }

    float4 m = *(const float4*)&M[(size_t)b*HW_ + h*W_ + wq];
    uint4 o;
    o.x = pack_hilo(leaky01(leaky01(dw.x)*m.x + mid_c.x));
    o.y = pack_hilo(leaky01(leaky01(dw.y)*m.y + mid_c.y));
    o.z = pack_hilo(leaky01(leaky01(dw.z)*m.z + mid_c.z));
    o.w = pack_hilo(leaky01(leaky01(dw.w)*m.w + mid_c.w));
    *(uint4*)&outp[((size_t)b*C_ + c)*HW_ + h*W_ + wq] = o;
}

// ---------------------------------------------------------------------------
// 3b) weight prep: fp32 OIHW -> bf16 hi/lo in m16n8k16 A-fragment order.
// ---------------------------------------------------------------------------
__global__ void wprep_kernel(const float* __restrict__ w1,
                             const float* __restrict__ w2)
{
    int idx = blockIdx.x * blockDim.x + threadIdx.x;
    if (idx >= 2*4*9*4*2*32*4) return;
    int t = idx;
    int r    = t & 3;  t >>= 2;
    int lane = t & 31; t >>= 5;
    int q    = t & 1;  t >>= 1;
    int mt   = t & 3;  t >>= 2;
    int s9   = t % 9;  t /= 9;
    int chunk= t & 3;  t >>= 2;
    int s2   = t;

    int g = lane >> 2, tig = lane & 3;
    int co = mt*16 + g + (r & 1)*8;
    int k0 = s9*16 + 2*tig + (r >> 1)*8;
    int k1 = k0 + 1;

    const float* w = s2 ? w2 : w1;
    int ci0 = k0/9, tap0 = k0 - ci0*9;
    int ci1 = k1/9, tap1 = k1 - ci1*9;
    float w0 = w[(co*C_ + chunk*16 + ci0)*9 + tap0];
    float w1v= w[(co*C_ + chunk*16 + ci1)*9 + tap1];

    u16 p0, p1;
    if (q == 0) {
        __nv_bfloat16 h0 = __float2bfloat16(w0), h1 = __float2bfloat16(w1v);
        p0 = *reinterpret_cast<u16*>(&h0); p1 = *reinterpret_cast<u16*>(&h1);
    } else {
        __nv_bfloat16 h0 = __float2bfloat16(w0);
        __nv_bfloat16 l0 = __float2bfloat16(w0 - __bfloat162float(h0));
        __nv_bfloat16 h1 = __float2bfloat16(w1v);
        __nv_bfloat16 l1 = __float2bfloat16(w1v - __bfloat162float(h1));
        p0 = *reinterpret_cast<u16*>(&l0); p1 = *reinterpret_cast<u16*>(&l1);
    }
    g_wA[idx] = ((u32)p1 << 16) | (u32)p0;
}

// ---------------------------------------------------------------------------
// 4) mma.sync conv v7: block = 1 row, 128 threads = 4 warps.
//    Full input slab in smem (one burst + one sync). Weights LDG.128
//    pipelined. MMAs issued TERM-MAJOR: each accumulator re-touched only
//    every 16 MMAs (no RAW chains on the HMMA pipe).
// ---------------------------------------------------------------------------
#define RW2  136
#define ICH_ALL (64*3*RW2)               // 26112 u32 = 104448 B
#define SMEM_DYN (ICH_ALL*4)

#define LOADFRAG(sg, AHs, ALs) do { \
    const u32* wb_ = wA + (u32)(sg)*1024 + lane*4; \
    AHs[0] = __ldg((const uint4*)(wb_        )); \
    ALs[0] = __ldg((const uint4*)(wb_ +  128)); \
    AHs[1] = __ldg((const uint4*)(wb_ +  256)); \
    ALs[1] = __ldg((const uint4*)(wb_ +  384)); \
    AHs[2] = __ldg((const uint4*)(wb_ +  512)); \
    ALs[2] = __ldg((const uint4*)(wb_ +  640)); \
    AHs[3] = __ldg((const uint4*)(wb_ +  768)); \
    ALs[3] = __ldg((const uint4*)(wb_ +  896)); \
} while (0)

__global__ void __launch_bounds__(128, 2)
conv_mma(const u32* __restrict__ pin,
         const u32* __restrict__ wA,
         const float* __restrict__ bias,
         const float* __restrict__ residual,
         float* __restrict__ out,
         int apply_leaky,
         const float* __restrict__ gcw,   // fused gate weights (or null)
         const float* __restrict__ gcb,
         float* __restrict__ Mout)
{
    extern __shared__ u32 inS[];

    int tid = threadIdx.x;
    int lane = tid & 31;
    int g = lane >> 2, tig = lane & 3;
    int warpbase = (tid >> 5) * 32;
    int h = blockIdx.x, b = blockIdx.z;

    // zero slab once (halo cols + off-image rows stay 0)
    for (int i = tid; i < ICH_ALL; i += 128) inS[i] = 0;
    u32 iS_a = smem_u32(inS);
    __syncthreads();

    // stage ALL input: 64 ci x 3 rows x 32 segs = 6144 x 16B (one burst)
#pragma unroll
    for (int i = 0; i < 48; i++) {
        int idx = tid + i*128;
        int ci  = idx / 96;
        int rem = idx - ci*96;
        int rr  = rem >> 5;
        int seg = rem & 31;
        int gy  = h - 1 + rr;
        if (gy >= 0 && gy < H_) {
            u32 dst = iS_a + (u32)(((ci*3 + rr)*RW2 + 4 + seg*4) * 4);
            cp_async16(dst, pin + (((size_t)b*C_ + ci)*H_ + gy)*W_ + seg*4);
        }
    }
    cp_commit();

    float D[4][4][4];
#pragma unroll
    for (int mt = 0; mt < 4; mt++)
#pragma unroll
        for (int nt = 0; nt < 4; nt++)
#pragma unroll
            for (int i = 0; i < 4; i++) D[mt][nt][i] = 0.f;

    cp_wait_all();
    __syncthreads();                         // slab ready; no more barriers

    uint4 AH[2][4], AL[2][4];

    for (int c9 = 0; c9 < 4; c9++) {
        LOADFRAG(c9*9, AH[0], AL[0]);
#pragma unroll
        for (int s = 0; s < 9; s++) {
            const int p = s & 1;
            if (s < 8) { LOADFRAG(c9*9 + s + 1, AH[p^1], AL[p^1]); }

            // hoist ALL B fragments for this K-step
            u32 bh[4][2], bl[4][2];
#pragma unroll
            for (int nt = 0; nt < 4; nt++) {
                int n = warpbase + nt*8 + g;
#pragma unroll
                for (int r = 0; r < 2; r++) {
                    int kl0 = s*16 + 2*tig + r*8;
                    int kl1 = kl0 + 1;
                    int ci0 = c9*16 + kl0/9, tap0 = kl0 % 9;
                    int ci1 = c9*16 + kl1/9, tap1 = kl1 % 9;
                    u32 v0 = inS[(ci0*3 + tap0/3)*RW2 + n + (tap0 % 3) + 3];
                    u32 v1 = inS[(ci1*3 + tap1/3)*RW2 + n + (tap1 % 3) + 3];
                    bh[nt][r] = __byte_perm(v0, v1, 0x7632);
                    bl[nt][r] = __byte_perm(v0, v1, 0x5410);
                }
            }

            // term-major issue: 16 independent MMAs between reuses of any D
#pragma unroll
            for (int nt = 0; nt < 4; nt++)
#pragma unroll
                for (int mt = 0; mt < 4; mt++)
                    mma16816(D[mt][nt], (const u32*)&AH[p][mt], bh[nt][0], bh[nt][1]);
#pragma unroll
            for (int nt = 0; nt < 4; nt++)
#pragma unroll
                for (int mt = 0; mt < 4; mt++)
                    mma16816(D[mt][nt], (const u32*)&AH[p][mt], bl[nt][0], bl[nt][1]);
#pragma unroll
            for (int nt = 0; nt < 4; nt++)
#pragma unroll
                for (int mt = 0; mt < 4; mt++)
                    mma16816(D[mt][nt], (const u32*)&AL[p][mt], bh[nt][0], bh[nt][1]);
        }
    }

    // ---- epilogue (+ optional fused gate) ----
    float bv[4][2], cwv[4][2];
#pragma unroll
    for (int mt = 0; mt < 4; mt++) {
        int co0 = mt*16 + g;
        bv[mt][0] = bias[co0];
        bv[mt][1] = bias[co0 + 8];
        if (gcw) { cwv[mt][0] = gcw[co0]; cwv[mt][1] = gcw[co0 + 8]; }
    }
    float gb = gcw ? gcb[0] : 0.f;

#pragma unroll
    for (int nt = 0; nt < 4; nt++) {
        int px = warpbase + nt*8 + 2*tig;
        float gx = 0.f, gy = 0.f;
#pragma unroll
        for (int mt = 0; mt < 4; mt++) {
            int co0 = mt*16 + g;
            size_t o0 = (((size_t)b*C_ + co0    )*H_ + h)*W_ + px;
            size_t o1 = (((size_t)b*C_ + co0 + 8)*H_ + h)*W_ + px;
            float2 v0 = make_float2(D[mt][nt][0] + bv[mt][0], D[mt][nt][1] + bv[mt][0]);
            float2 v1 = make_float2(D[mt][nt][2] + bv[mt][1], D[mt][nt][3] + bv[mt][1]);
            if (apply_leaky) {
                v0.x = leaky01(v0.x); v0.y = leaky01(v0.y);
                v1.x = leaky01(v1.x); v1.y = leaky01(v1.y);
            }
            if (residual) {
                const float2 r0 = *(const float2*)&residual[o0];
                const float2 r1 = *(const float2*)&residual[o1];
                v0.x += r0.x; v0.y += r0.y; v1.x += r1.x; v1.y += r1.y;
            }
            *(float2*)&out[o0] = v0;
            *(float2*)&out[o1] = v1;
            if (gcw) {
                gx += v0.x*cwv[mt][0] + v1.x*cwv[mt][1];
                gy += v0.y*cwv[mt][0] + v1.y*cwv[mt][1];
            }
        }
        if (gcw) {
#pragma unroll
            for (int ofs = 4; ofs <= 16; ofs <<= 1) {
                gx += __shfl_xor_sync(0xFFFFFFFFu, gx, ofs);
                gy += __shfl_xor_sync(0xFFFFFFFFu, gy, ofs);
            }
            if (g == 0) {
                float2 mo;
                mo.x = 1.f / (1.f + expf(-(gx + gb)));
                mo.y = 1.f / (1.f + expf(-(gy + gb)));
                *(float2*)&Mout[(size_t)b*HW_ + h*W_ + px] = mo;
            }
        }
    }
}

// ---------------------------------------------------------------------------
// launch
// ---------------------------------------------------------------------------
extern "C" void kernel_launch(void* const* d_in, const int* in_sizes, int n_in,
                              void* d_out, int out_size)
{
    const float* x       = (const float*)d_in[0];
    const float* d       = (const float*)d_in[1];
    const float* da1_k1  = (const float*)d_in[2];
    const float* da1_k2  = (const float*)d_in[3];
    const float* da1_cw  = (const float*)d_in[4];
    const float* da1_cb  = (const float*)d_in[5];
    const float* da2_k1  = (const float*)d_in[6];
    const float* da2_k2  = (const float*)d_in[7];
    const float* da2_cw  = (const float*)d_in[8];
    const float* da2_cb  = (const float*)d_in[9];
    const float* conv1_w = (const float*)d_in[10];
    const float* conv1_b = (const float*)d_in[11];
    const float* conv2_w = (const float*)d_in[12];
    const float* conv2_b = (const float*)d_in[13];
    float* out = (float*)d_out;

    u32 *buf1, *wa; float *buf2, *gate, *kern1, *kern2;
    cudaGetSymbolAddress((void**)&buf1,  g_buf1);
    cudaGetSymbolAddress((void**)&buf2,  g_buf2);
    cudaGetSymbolAddress((void**)&gate,  g_gate);
    cudaGetSymbolAddress((void**)&kern1, g_kern1);
    cudaGetSymbolAddress((void**)&kern2, g_kern2);
    cudaGetSymbolAddress((void**)&wa,    g_wA);

    cudaFuncSetAttribute(conv_mma, cudaFuncAttributeMaxDynamicSharedMemorySize, SMEM_DYN);

    mlp_kernel<<<dim3(B_, 2), 64>>>(d, da1_k1, da1_k2, da2_k1, da2_k2, kern1, kern2);
    wprep_kernel<<<(2*4*9*4*2*32*4 + 255)/256, 256>>>(conv1_w, conv2_w);

    gate_kernel<<<(B_*HW_/4)/256, 256>>>(x, da1_cw, da1_cb, gate);
    rda_kernel<<<dim3(HW_/4/256, C_, B_), 256>>>(x, kern1, gate, buf1);

    // conv1 + leaky, with fused gate2 (writes M for rda2 into `gate`)
    conv_mma<<<dim3(H_, 1, B_), 128, SMEM_DYN>>>(buf1, wa, conv1_b, nullptr,
                                                 buf2, 1, da2_cw, da2_cb, gate);

    rda_kernel<<<dim3(HW_/4/256, C_, B_), 256>>>(buf2, kern2, gate, buf1);

    // conv2 + residual(x)
    conv_mma<<<dim3(H_, 1, B_), 128, SMEM_DYN>>>(buf1, wa + 4*9216, conv2_b, x,
                                                 out, 0, nullptr, nullptr, nullptr);
}